// round 2
// baseline (speedup 1.0000x reference)
#include <cuda_runtime.h>
#include <math.h>

#define DIMS 64
#define MAXB 8192
#define TPB_SEL 256
#define NPT 32          // values per thread in select: 256 * 32 = 8192

// Scratch (static device allocations are the sanctioned scratch mechanism).
static __device__ float g_d2[(size_t)MAXB * (size_t)MAXB];  // 256 MB
static __device__ float g_sq[MAXB];
static __device__ int   g_hard[MAXB];
static __device__ int   g_gcounts[64];

// ---------------------------------------------------------------------------
// Zero the global cluster counters (graph-replay safe: re-zeroed every launch)
// ---------------------------------------------------------------------------
__global__ void zero_kernel() {
    if (threadIdx.x < 64) g_gcounts[threadIdx.x] = 0;
}

// ---------------------------------------------------------------------------
// Per-row: squared norm of encodings, argmax/max of categorical, global counts
// One warp per row.
// ---------------------------------------------------------------------------
__global__ void stats_kernel(const float* __restrict__ E,
                             const float* __restrict__ Cat,
                             float* __restrict__ out_maxg,
                             int B, int C) {
    int warp = (blockIdx.x * blockDim.x + threadIdx.x) >> 5;
    int lane = threadIdx.x & 31;
    if (warp >= B) return;

    // squared norm over D=64 (two loads per lane)
    float v0 = E[(size_t)warp * DIMS + lane];
    float v1 = E[(size_t)warp * DIMS + 32 + lane];
    float s = v0 * v0 + v1 * v1;
    #pragma unroll
    for (int off = 16; off; off >>= 1) s += __shfl_xor_sync(0xffffffffu, s, off);

    // argmax over C components (first-occurrence tie-break, matches jnp.argmax)
    float mv = -INFINITY;
    int   mi = 0x7fffffff;
    for (int c = lane; c < C; c += 32) {
        float x = Cat[(size_t)warp * C + c];
        if (x > mv) { mv = x; mi = c; }
    }
    #pragma unroll
    for (int off = 16; off; off >>= 1) {
        float ov = __shfl_xor_sync(0xffffffffu, mv, off);
        int   oi = __shfl_xor_sync(0xffffffffu, mi, off);
        if (ov > mv || (ov == mv && oi < mi)) { mv = ov; mi = oi; }
    }

    if (lane == 0) {
        g_sq[warp]   = s;
        g_hard[warp] = mi;
        out_maxg[warp] = mv;
        atomicAdd(&g_gcounts[mi], 1);
    }
}

// ---------------------------------------------------------------------------
// Tiled fp32 GEMM producing the squared-distance matrix directly.
// 64x64 output tile per block, K=64 fully resident in shared (transposed),
// 4x4 register micro-tile per thread, float4 shared reads.
// ---------------------------------------------------------------------------
__global__ void __launch_bounds__(256) gemm_kernel(const float* __restrict__ E, int B) {
    __shared__ float As[DIMS][64 + 4];   // [k][i], pad keeps float4 alignment
    __shared__ float Bs[DIMS][64 + 4];   // [k][j]

    int i0 = blockIdx.y * 64;
    int j0 = blockIdx.x * 64;
    int tid = threadIdx.x;

    // cooperative load: 64 rows x 64 cols for each tile, transposed into smem
    int lr = tid >> 4;          // 0..15
    int lc = (tid & 15) << 2;   // 0..60 step 4
    #pragma unroll
    for (int it = 0; it < 4; ++it) {
        int r = lr + it * 16;
        float4 a = *(const float4*)(E + (size_t)(i0 + r) * DIMS + lc);
        As[lc + 0][r] = a.x; As[lc + 1][r] = a.y;
        As[lc + 2][r] = a.z; As[lc + 3][r] = a.w;
        float4 b = *(const float4*)(E + (size_t)(j0 + r) * DIMS + lc);
        Bs[lc + 0][r] = b.x; Bs[lc + 1][r] = b.y;
        Bs[lc + 2][r] = b.z; Bs[lc + 3][r] = b.w;
    }
    __syncthreads();

    int isub = (tid >> 4) << 2;   // 0..60
    int jsub = (tid & 15) << 2;   // 0..60

    float acc[4][4];
    #pragma unroll
    for (int a = 0; a < 4; ++a)
        #pragma unroll
        for (int b = 0; b < 4; ++b) acc[a][b] = 0.f;

    #pragma unroll
    for (int k = 0; k < DIMS; ++k) {
        float4 av = *(const float4*)&As[k][isub];
        float4 bv = *(const float4*)&Bs[k][jsub];
        float aa[4] = {av.x, av.y, av.z, av.w};
        float bb[4] = {bv.x, bv.y, bv.z, bv.w};
        #pragma unroll
        for (int ii = 0; ii < 4; ++ii)
            #pragma unroll
            for (int jj = 0; jj < 4; ++jj)
                acc[ii][jj] += aa[ii] * bb[jj];
    }

    // epilogue: d2 = sq_i + sq_j - 2*dot, clamped to +0 (bit-pattern 0x0)
    float sqi[4], sqj[4];
    #pragma unroll
    for (int t = 0; t < 4; ++t) {
        sqi[t] = g_sq[i0 + isub + t];
        sqj[t] = g_sq[j0 + jsub + t];
    }
    #pragma unroll
    for (int ii = 0; ii < 4; ++ii) {
        float4 o;
        float d;
        d = sqi[ii] + sqj[0] - 2.f * acc[ii][0]; o.x = (d > 0.f) ? d : 0.f;
        d = sqi[ii] + sqj[1] - 2.f * acc[ii][1]; o.y = (d > 0.f) ? d : 0.f;
        d = sqi[ii] + sqj[2] - 2.f * acc[ii][2]; o.z = (d > 0.f) ? d : 0.f;
        d = sqi[ii] + sqj[3] - 2.f * acc[ii][3]; o.w = (d > 0.f) ? d : 0.f;
        *(float4*)(g_d2 + (size_t)(i0 + isub + ii) * B + j0 + jsub) = o;
    }
}

// ---------------------------------------------------------------------------
// Per-row selection + neighborhood entropy.
// One block per row. Values live in registers; the exact (k+1)-th smallest
// value is found by binary search over IEEE bit patterns (monotone for >=0
// floats), using block-reduced counts. Then strict-< threshold histogram.
// ---------------------------------------------------------------------------
__global__ void __launch_bounds__(TPB_SEL) select_kernel(const int* __restrict__ kptr,
                                                         float* __restrict__ out_ent,
                                                         int B, int C) {
    int i    = blockIdx.x;
    int tid  = threadIdx.x;
    int lane = tid & 31;
    int wid  = tid >> 5;

    int k = *kptr;
    if (k > B / 4) k = B / 4;
    int kk = k + 1;               // (k+1)-th smallest, self-distance included

    const float* row = g_d2 + (size_t)i * B;
    unsigned vb[NPT];
    #pragma unroll
    for (int s = 0; s < NPT; ++s) {
        int j = tid + s * TPB_SEL;
        vb[s] = (j < B) ? __float_as_uint(row[j]) : 0x7fffffffu;
    }

    __shared__ int sred[8];
    __shared__ int counts[64];

    // radix binary search for the kk-th order statistic (exact, handles ties)
    unsigned prefix = 0u;
    for (int b = 31; b >= 0; --b) {
        unsigned cand = prefix | (1u << b);
        int c = 0;
        #pragma unroll
        for (int s = 0; s < NPT; ++s) c += (vb[s] < cand);
        #pragma unroll
        for (int off = 16; off; off >>= 1) c += __shfl_xor_sync(0xffffffffu, c, off);
        if (lane == 0) sred[wid] = c;
        __syncthreads();
        int tot = sred[0] + sred[1] + sred[2] + sred[3] +
                  sred[4] + sred[5] + sred[6] + sred[7];
        if (tot < kk) prefix = cand;   // uniform decision across the block
        __syncthreads();
    }
    // prefix == bit pattern of the kk-th smallest distance

    if (tid < 64) counts[tid] = 0;
    __syncthreads();

    #pragma unroll
    for (int s = 0; s < NPT; ++s) {
        int j = tid + s * TPB_SEL;
        if (j < B && vb[s] < prefix)           // strict <, matches reference mask
            atomicAdd(&counts[g_hard[j]], 1);
    }
    __syncthreads();

    if (wid == 0) {
        float cnt = (lane < C) ? (float)counts[lane] : 0.f;
        float n = cnt;
        #pragma unroll
        for (int off = 16; off; off >>= 1) n += __shfl_xor_sync(0xffffffffu, n, off);
        float ni = (n > 1.f) ? n : 1.f;
        float bfrac = cnt / ni;
        float h = -bfrac * logf(bfrac + 1e-5f);
        #pragma unroll
        for (int off = 16; off; off >>= 1) h += __shfl_xor_sync(0xffffffffu, h, off);
        if (lane == 0) out_ent[i] = h;
    }
}

// ---------------------------------------------------------------------------
// Global cluster-size entropy + populated-cluster count (single warp).
// ---------------------------------------------------------------------------
__global__ void finalize_kernel(float* __restrict__ out2, int B, int C) {
    int lane = threadIdx.x;
    float g  = (lane < C) ? (float)g_gcounts[lane] : 0.f;
    float gb = g / (float)B;
    float h  = -gb * logf(gb + 1e-5f);
    float p  = (lane < C && g > 0.f) ? 1.f : 0.f;
    #pragma unroll
    for (int off = 16; off; off >>= 1) {
        h += __shfl_xor_sync(0xffffffffu, h, off);
        p += __shfl_xor_sync(0xffffffffu, p, off);
    }
    if (lane == 0) { out2[0] = h; out2[1] = p; }
}

// ---------------------------------------------------------------------------
// Output layout (flattened reference tuple):
//   [0, B*64)            encodings passthrough
//   [B*64, B*64+B)       neighbourhood_entropy
//   [B*64+B]             cluster_size_entropy
//   [B*64+B+1]           n_populated
//   [B*64+B+2, +B)       max_groups
// ---------------------------------------------------------------------------
extern "C" void kernel_launch(void* const* d_in, const int* in_sizes, int n_in,
                              void* d_out, int out_size) {
    const float* E    = (const float*)d_in[0];
    const float* Cat  = (const float*)d_in[1];
    const int*   kptr = (const int*)d_in[2];

    int B = in_sizes[0] / DIMS;
    int C = in_sizes[1] / B;

    float* out      = (float*)d_out;
    float* out_ent  = out + (size_t)B * DIMS;
    float* out_sc   = out_ent + B;
    float* out_maxg = out_sc + 2;

    cudaMemcpyAsync(out, E, (size_t)B * DIMS * sizeof(float),
                    cudaMemcpyDeviceToDevice, 0);

    zero_kernel<<<1, 64>>>();
    stats_kernel<<<(B * 32 + 255) / 256, 256>>>(E, Cat, out_maxg, B, C);
    gemm_kernel<<<dim3(B / 64, B / 64), 256>>>(E, B);
    select_kernel<<<B, TPB_SEL>>>(kptr, out_ent, B, C);
    finalize_kernel<<<1, 32>>>(out_sc, B, C);
}

// round 3
// speedup vs baseline: 1.2059x; 1.2059x over previous
#include <cuda_runtime.h>
#include <math.h>

#define DIMS 64
#define MAXB 8192
#define TPB_SEL 256
#define CAP 4096        // candidate buffer (expected ~20-40 entries for k=15)

// Scratch (static device allocations are the sanctioned scratch mechanism).
static __device__ float g_d2[(size_t)MAXB * (size_t)MAXB];  // 256 MB
static __device__ float g_sq[MAXB];
static __device__ int   g_hard[MAXB];
static __device__ int   g_gcounts[64];

// ---------------------------------------------------------------------------
__global__ void zero_kernel() {
    if (threadIdx.x < 64) g_gcounts[threadIdx.x] = 0;
}

// ---------------------------------------------------------------------------
// Per-row: squared norm, argmax/max of categorical, global cluster counts.
// ---------------------------------------------------------------------------
__global__ void stats_kernel(const float* __restrict__ E,
                             const float* __restrict__ Cat,
                             float* __restrict__ out_maxg,
                             int B, int C) {
    int warp = (blockIdx.x * blockDim.x + threadIdx.x) >> 5;
    int lane = threadIdx.x & 31;
    if (warp >= B) return;

    float v0 = E[(size_t)warp * DIMS + lane];
    float v1 = E[(size_t)warp * DIMS + 32 + lane];
    float s = v0 * v0 + v1 * v1;
    #pragma unroll
    for (int off = 16; off; off >>= 1) s += __shfl_xor_sync(0xffffffffu, s, off);

    float mv = -INFINITY;
    int   mi = 0x7fffffff;
    for (int c = lane; c < C; c += 32) {
        float x = Cat[(size_t)warp * C + c];
        if (x > mv) { mv = x; mi = c; }
    }
    #pragma unroll
    for (int off = 16; off; off >>= 1) {
        float ov = __shfl_xor_sync(0xffffffffu, mv, off);
        int   oi = __shfl_xor_sync(0xffffffffu, mi, off);
        if (ov > mv || (ov == mv && oi < mi)) { mv = ov; mi = oi; }
    }

    if (lane == 0) {
        g_sq[warp]   = s;
        g_hard[warp] = mi;
        out_maxg[warp] = mv;
        atomicAdd(&g_gcounts[mi], 1);
    }
}

// ---------------------------------------------------------------------------
// Tiled fp32 GEMM producing the squared-distance matrix (at FFMA roofline).
// ---------------------------------------------------------------------------
__global__ void __launch_bounds__(256) gemm_kernel(const float* __restrict__ E, int B) {
    __shared__ float As[DIMS][64 + 4];
    __shared__ float Bs[DIMS][64 + 4];

    int i0 = blockIdx.y * 64;
    int j0 = blockIdx.x * 64;
    int tid = threadIdx.x;

    int lr = tid >> 4;
    int lc = (tid & 15) << 2;
    #pragma unroll
    for (int it = 0; it < 4; ++it) {
        int r = lr + it * 16;
        float4 a = *(const float4*)(E + (size_t)(i0 + r) * DIMS + lc);
        As[lc + 0][r] = a.x; As[lc + 1][r] = a.y;
        As[lc + 2][r] = a.z; As[lc + 3][r] = a.w;
        float4 b = *(const float4*)(E + (size_t)(j0 + r) * DIMS + lc);
        Bs[lc + 0][r] = b.x; Bs[lc + 1][r] = b.y;
        Bs[lc + 2][r] = b.z; Bs[lc + 3][r] = b.w;
    }
    __syncthreads();

    int isub = (tid >> 4) << 2;
    int jsub = (tid & 15) << 2;

    float acc[4][4];
    #pragma unroll
    for (int a = 0; a < 4; ++a)
        #pragma unroll
        for (int b = 0; b < 4; ++b) acc[a][b] = 0.f;

    #pragma unroll
    for (int k = 0; k < DIMS; ++k) {
        float4 av = *(const float4*)&As[k][isub];
        float4 bv = *(const float4*)&Bs[k][jsub];
        float aa[4] = {av.x, av.y, av.z, av.w};
        float bb[4] = {bv.x, bv.y, bv.z, bv.w};
        #pragma unroll
        for (int ii = 0; ii < 4; ++ii)
            #pragma unroll
            for (int jj = 0; jj < 4; ++jj)
                acc[ii][jj] += aa[ii] * bb[jj];
    }

    float sqi[4], sqj[4];
    #pragma unroll
    for (int t = 0; t < 4; ++t) {
        sqi[t] = g_sq[i0 + isub + t];
        sqj[t] = g_sq[j0 + jsub + t];
    }
    #pragma unroll
    for (int ii = 0; ii < 4; ++ii) {
        float4 o;
        float d;
        d = sqi[ii] + sqj[0] - 2.f * acc[ii][0]; o.x = (d > 0.f) ? d : 0.f;
        d = sqi[ii] + sqj[1] - 2.f * acc[ii][1]; o.y = (d > 0.f) ? d : 0.f;
        d = sqi[ii] + sqj[2] - 2.f * acc[ii][2]; o.z = (d > 0.f) ? d : 0.f;
        d = sqi[ii] + sqj[3] - 2.f * acc[ii][3]; o.w = (d > 0.f) ? d : 0.f;
        *(float4*)(g_d2 + (size_t)(i0 + isub + ii) * B + j0 + jsub) = o;
    }
}

// ---------------------------------------------------------------------------
// Selection via guaranteed subset-pruning:
//  - 256 thread-minima form a subset; its kk-th smallest >= global kk-th.
//  - Compact values <= that bound (~tens), exact radix-select among them.
//  - Histogram pass uses the exact kth bit pattern (strict <, tie-exact).
// ---------------------------------------------------------------------------
__global__ void __launch_bounds__(TPB_SEL) select_kernel(const int* __restrict__ kptr,
                                                         float* __restrict__ out_ent,
                                                         int B, int C) {
    int i    = blockIdx.x;
    int tid  = threadIdx.x;
    int lane = tid & 31;
    int wid  = tid >> 5;

    int k = *kptr;
    if (k > B / 4) k = B / 4;
    int kk = k + 1;               // (k+1)-th smallest, self-distance included

    __shared__ unsigned sm_min[TPB_SEL];
    __shared__ unsigned cand[CAP];
    __shared__ int      ncand;
    __shared__ unsigned sh_tub, sh_kth;
    __shared__ int      counts[64];

    // Load row (uint bit patterns; all values >= +0 so uint order == float order)
    const uint4* row4 = (const uint4*)(g_d2 + (size_t)i * B);
    unsigned v[32];
    unsigned mn = 0xffffffffu;
    #pragma unroll
    for (int s = 0; s < 8; ++s) {
        uint4 q = row4[tid + s * TPB_SEL];       // B = 8192: 2048 uint4 per row
        v[4 * s + 0] = q.x; v[4 * s + 1] = q.y;
        v[4 * s + 2] = q.z; v[4 * s + 3] = q.w;
        unsigned m01 = min(q.x, q.y), m23 = min(q.z, q.w);
        mn = min(mn, min(m01, m23));
    }
    sm_min[tid] = mn;
    if (tid < 64) counts[tid] = 0;
    if (tid == 0) ncand = 0;
    __syncthreads();

    // Warp 0: T_ub = kk-th smallest of the 256 thread-minima (guaranteed upper
    // bound on the global kk-th smallest). Fallback: +inf if kk > 256.
    if (wid == 0) {
        unsigned tub;
        if (kk <= TPB_SEL) {
            unsigned prefix = 0u;
            for (int b = 31; b >= 0; --b) {
                unsigned t = prefix | (1u << b);
                int c = 0;
                #pragma unroll
                for (int s = 0; s < 8; ++s) c += (sm_min[lane + 32 * s] < t);
                #pragma unroll
                for (int off = 16; off; off >>= 1) c += __shfl_xor_sync(0xffffffffu, c, off);
                if (c < kk) prefix = t;
            }
            tub = prefix;
        } else {
            tub = 0x7f800000u;   // +inf: all values become candidates
        }
        if (lane == 0) sh_tub = tub;
    }
    __syncthreads();

    // Compact candidates (v <= T_ub); contains all kk smallest by construction.
    unsigned tub = sh_tub;
    #pragma unroll
    for (int s = 0; s < 32; ++s) {
        if (v[s] <= tub) {
            int p = atomicAdd(&ncand, 1);
            if (p < CAP) cand[p] = v[s];
        }
    }
    __syncthreads();

    // Warp 0: exact kk-th smallest among candidates == exact global kk-th.
    int n = ncand; if (n > CAP) n = CAP;
    if (wid == 0) {
        unsigned prefix = 0u;
        for (int b = 31; b >= 0; --b) {
            unsigned t = prefix | (1u << b);
            int c = 0;
            for (int idx = lane; idx < n; idx += 32) c += (cand[idx] < t);
            #pragma unroll
            for (int off = 16; off; off >>= 1) c += __shfl_xor_sync(0xffffffffu, c, off);
            if (c < kk) prefix = t;
        }
        if (lane == 0) sh_kth = prefix;
    }
    __syncthreads();

    // Histogram of neighbor labels: strict v < kth (exact bit comparison).
    unsigned kth = sh_kth;
    #pragma unroll
    for (int s = 0; s < 32; ++s) {
        if (v[s] < kth) {
            int j = 4 * (tid + (s >> 2) * TPB_SEL) + (s & 3);
            atomicAdd(&counts[g_hard[j]], 1);
        }
    }
    __syncthreads();

    if (wid == 0) {
        float cnt = (lane < C) ? (float)counts[lane] : 0.f;
        float nn = cnt;
        #pragma unroll
        for (int off = 16; off; off >>= 1) nn += __shfl_xor_sync(0xffffffffu, nn, off);
        float ni = (nn > 1.f) ? nn : 1.f;
        float bfrac = cnt / ni;
        float h = -bfrac * logf(bfrac + 1e-5f);
        #pragma unroll
        for (int off = 16; off; off >>= 1) h += __shfl_xor_sync(0xffffffffu, h, off);
        if (lane == 0) out_ent[i] = h;
    }
}

// ---------------------------------------------------------------------------
__global__ void finalize_kernel(float* __restrict__ out2, int B, int C) {
    int lane = threadIdx.x;
    float g  = (lane < C) ? (float)g_gcounts[lane] : 0.f;
    float gb = g / (float)B;
    float h  = -gb * logf(gb + 1e-5f);
    float p  = (lane < C && g > 0.f) ? 1.f : 0.f;
    #pragma unroll
    for (int off = 16; off; off >>= 1) {
        h += __shfl_xor_sync(0xffffffffu, h, off);
        p += __shfl_xor_sync(0xffffffffu, p, off);
    }
    if (lane == 0) { out2[0] = h; out2[1] = p; }
}

// ---------------------------------------------------------------------------
// Output layout (flattened reference tuple):
//   [0, B*64)            encodings passthrough
//   [B*64, B*64+B)       neighbourhood_entropy
//   [B*64+B]             cluster_size_entropy
//   [B*64+B+1]           n_populated
//   [B*64+B+2, +B)       max_groups
// ---------------------------------------------------------------------------
extern "C" void kernel_launch(void* const* d_in, const int* in_sizes, int n_in,
                              void* d_out, int out_size) {
    const float* E    = (const float*)d_in[0];
    const float* Cat  = (const float*)d_in[1];
    const int*   kptr = (const int*)d_in[2];

    int B = in_sizes[0] / DIMS;
    int C = in_sizes[1] / B;

    float* out      = (float*)d_out;
    float* out_ent  = out + (size_t)B * DIMS;
    float* out_sc   = out_ent + B;
    float* out_maxg = out_sc + 2;

    cudaMemcpyAsync(out, E, (size_t)B * DIMS * sizeof(float),
                    cudaMemcpyDeviceToDevice, 0);

    zero_kernel<<<1, 64>>>();
    stats_kernel<<<(B * 32 + 255) / 256, 256>>>(E, Cat, out_maxg, B, C);
    gemm_kernel<<<dim3(B / 64, B / 64), 256>>>(E, B);
    select_kernel<<<B, TPB_SEL>>>(kptr, out_ent, B, C);
    finalize_kernel<<<1, 32>>>(out_sc, B, C);
}

// round 5
// speedup vs baseline: 1.6113x; 1.3361x over previous
#include <cuda_runtime.h>
#include <math.h>

#define DIMS 64
#define MAXB 8192
#define TPB_SEL 256
#define CAP 4096        // candidate buffer (expected ~20-40 entries for k=15)

// Scratch (static device allocations are the sanctioned scratch mechanism).
static __device__ float g_d2[(size_t)MAXB * (size_t)MAXB];  // 256 MB
static __device__ float g_sq[MAXB];
static __device__ int   g_hard[MAXB];
static __device__ int   g_gcounts[64];

// ---------------------------------------------------------------------------
__global__ void zero_kernel() {
    if (threadIdx.x < 64) g_gcounts[threadIdx.x] = 0;
}

// ---------------------------------------------------------------------------
// Per-row: squared norm, argmax/max of categorical, global cluster counts.
// ---------------------------------------------------------------------------
__global__ void stats_kernel(const float* __restrict__ E,
                             const float* __restrict__ Cat,
                             float* __restrict__ out_maxg,
                             int B, int C) {
    int warp = (blockIdx.x * blockDim.x + threadIdx.x) >> 5;
    int lane = threadIdx.x & 31;
    if (warp >= B) return;

    float v0 = E[(size_t)warp * DIMS + lane];
    float v1 = E[(size_t)warp * DIMS + 32 + lane];
    float s = v0 * v0 + v1 * v1;
    #pragma unroll
    for (int off = 16; off; off >>= 1) s += __shfl_xor_sync(0xffffffffu, s, off);

    float mv = -INFINITY;
    int   mi = 0x7fffffff;
    for (int c = lane; c < C; c += 32) {
        float x = Cat[(size_t)warp * C + c];
        if (x > mv) { mv = x; mi = c; }
    }
    #pragma unroll
    for (int off = 16; off; off >>= 1) {
        float ov = __shfl_xor_sync(0xffffffffu, mv, off);
        int   oi = __shfl_xor_sync(0xffffffffu, mi, off);
        if (ov > mv || (ov == mv && oi < mi)) { mv = ov; mi = oi; }
    }

    if (lane == 0) {
        g_sq[warp]   = s;
        g_hard[warp] = mi;
        out_maxg[warp] = mv;
        atomicAdd(&g_gcounts[mi], 1);
    }
}

// ---------------------------------------------------------------------------
// Tiled fp32 GEMM producing the squared-distance matrix (at FFMA roofline).
// ---------------------------------------------------------------------------
__global__ void __launch_bounds__(256) gemm_kernel(const float* __restrict__ E, int B) {
    __shared__ float As[DIMS][64 + 4];
    __shared__ float Bs[DIMS][64 + 4];

    int i0 = blockIdx.y * 64;
    int j0 = blockIdx.x * 64;
    int tid = threadIdx.x;

    int lr = tid >> 4;
    int lc = (tid & 15) << 2;
    #pragma unroll
    for (int it = 0; it < 4; ++it) {
        int r = lr + it * 16;
        float4 a = *(const float4*)(E + (size_t)(i0 + r) * DIMS + lc);
        As[lc + 0][r] = a.x; As[lc + 1][r] = a.y;
        As[lc + 2][r] = a.z; As[lc + 3][r] = a.w;
        float4 b = *(const float4*)(E + (size_t)(j0 + r) * DIMS + lc);
        Bs[lc + 0][r] = b.x; Bs[lc + 1][r] = b.y;
        Bs[lc + 2][r] = b.z; Bs[lc + 3][r] = b.w;
    }
    __syncthreads();

    int isub = (tid >> 4) << 2;
    int jsub = (tid & 15) << 2;

    float acc[4][4];
    #pragma unroll
    for (int a = 0; a < 4; ++a)
        #pragma unroll
        for (int b = 0; b < 4; ++b) acc[a][b] = 0.f;

    #pragma unroll
    for (int k = 0; k < DIMS; ++k) {
        float4 av = *(const float4*)&As[k][isub];
        float4 bv = *(const float4*)&Bs[k][jsub];
        float aa[4] = {av.x, av.y, av.z, av.w};
        float bb[4] = {bv.x, bv.y, bv.z, bv.w};
        #pragma unroll
        for (int ii = 0; ii < 4; ++ii)
            #pragma unroll
            for (int jj = 0; jj < 4; ++jj)
                acc[ii][jj] += aa[ii] * bb[jj];
    }

    float sqi[4], sqj[4];
    #pragma unroll
    for (int t = 0; t < 4; ++t) {
        sqi[t] = g_sq[i0 + isub + t];
        sqj[t] = g_sq[j0 + jsub + t];
    }
    #pragma unroll
    for (int ii = 0; ii < 4; ++ii) {
        float4 o;
        float d;
        d = sqi[ii] + sqj[0] - 2.f * acc[ii][0]; o.x = (d > 0.f) ? d : 0.f;
        d = sqi[ii] + sqj[1] - 2.f * acc[ii][1]; o.y = (d > 0.f) ? d : 0.f;
        d = sqi[ii] + sqj[2] - 2.f * acc[ii][2]; o.z = (d > 0.f) ? d : 0.f;
        d = sqi[ii] + sqj[3] - 2.f * acc[ii][3]; o.w = (d > 0.f) ? d : 0.f;
        *(float4*)(g_d2 + (size_t)(i0 + isub + ii) * B + j0 + jsub) = o;
    }
}

// ---------------------------------------------------------------------------
// Per-row selection + neighborhood entropy.
// Phase 1: 256 thread-minima -> 32 lane-minima (disjoint subsets), exact
//          kk-th of those 32 via warp rank-trick = guaranteed upper bound.
// Phase 2: compact v <= bound (~tens), exact kk-th via rank-trick (n<=32)
//          or warp radix (n<=CAP). Block-wide radix fallback for the rest.
// All comparisons on IEEE bit patterns (values clamped >= +0 => monotone).
// ---------------------------------------------------------------------------
__global__ void __launch_bounds__(TPB_SEL) select_kernel(const int* __restrict__ kptr,
                                                         float* __restrict__ out_ent,
                                                         int B, int C) {
    int i    = blockIdx.x;
    int tid  = threadIdx.x;
    int lane = tid & 31;
    int wid  = tid >> 5;

    int k = *kptr;
    if (k > B / 4) k = B / 4;
    int kk = k + 1;               // (k+1)-th smallest, self-distance included

    __shared__ unsigned sm_min[TPB_SEL];
    __shared__ unsigned cand[CAP];
    __shared__ int      ncand;
    __shared__ unsigned sh_tub, sh_kth;
    __shared__ int      counts[64];
    __shared__ int      sred[8];

    // Load row as bit patterns; thread-min on the fly.
    const uint4* row4 = (const uint4*)(g_d2 + (size_t)i * B);
    unsigned v[32];
    unsigned mn = 0xffffffffu;
    #pragma unroll
    for (int s = 0; s < 8; ++s) {
        uint4 q = row4[tid + s * TPB_SEL];       // B = 8192: 2048 uint4 per row
        v[4 * s + 0] = q.x; v[4 * s + 1] = q.y;
        v[4 * s + 2] = q.z; v[4 * s + 3] = q.w;
        unsigned m01 = min(q.x, q.y), m23 = min(q.z, q.w);
        mn = min(mn, min(m01, m23));
    }
    sm_min[tid] = mn;
    if (tid < 64) counts[tid] = 0;
    if (tid == 0) ncand = 0;
    __syncthreads();

    // ---- Phase 1: upper bound on the global kk-th smallest ----
    if (wid == 0) {
        unsigned tub;
        if (kk <= 32) {
            // lane-min over 8 strided thread-minima (disjoint 256-value subsets)
            unsigned m = sm_min[lane];
            #pragma unroll
            for (int s = 1; s < 8; ++s) m = min(m, sm_min[lane + 32 * s]);
            // exact kk-th smallest of the 32 minima via rank-trick
            int cls = 0, cle = 0;
            #pragma unroll
            for (int j = 0; j < 32; ++j) {
                unsigned b = __shfl_sync(0xffffffffu, m, j);
                cls += (b < m);
                cle += (b <= m);
            }
            bool sel = (cls < kk) && (cle >= kk);
            unsigned ball = __ballot_sync(0xffffffffu, sel);
            tub = __shfl_sync(0xffffffffu, m, __ffs(ball) - 1);
        } else {
            tub = 0xffffffffu;   // sentinel: take the full-scan fallback
        }
        if (lane == 0) sh_tub = tub;
    }
    __syncthreads();

    // ---- Compact candidates (v <= bound) ----
    unsigned tub = sh_tub;
    bool fullscan = (tub == 0xffffffffu);
    if (!fullscan) {
        #pragma unroll
        for (int s = 0; s < 32; ++s) {
            if (v[s] <= tub) {
                int p = atomicAdd(&ncand, 1);
                if (p < CAP) cand[p] = v[s];
            }
        }
    }
    __syncthreads();

    int n = ncand;
    // ---- Phase 2: exact global kk-th smallest ----
    if (fullscan || n > CAP) {
        // Block-wide exact radix over all register values (rare / generic path).
        unsigned prefix = 0u;
        for (int b = 30; b >= 0; --b) {            // sign bit is always 0
            unsigned t = prefix | (1u << b);
            int c = 0;
            #pragma unroll
            for (int s = 0; s < 32; ++s) c += (v[s] < t);
            #pragma unroll
            for (int off = 16; off; off >>= 1) c += __shfl_xor_sync(0xffffffffu, c, off);
            if (lane == 0) sred[wid] = c;
            __syncthreads();
            int tot = sred[0] + sred[1] + sred[2] + sred[3] +
                      sred[4] + sred[5] + sred[6] + sred[7];
            if (tot < kk) prefix = t;
            __syncthreads();
        }
        if (tid == 0) sh_kth = prefix;
    } else if (wid == 0) {
        unsigned kth;
        if (n <= 32) {
            // rank-trick among <=32 candidates (kk <= 32 <= n guaranteed here)
            unsigned c = (lane < n) ? cand[lane] : 0xffffffffu;
            int cls = 0, cle = 0;
            for (int j = 0; j < n; ++j) {
                unsigned b = __shfl_sync(0xffffffffu, c, j);
                cls += (b < c);
                cle += (b <= c);
            }
            bool sel = (cls < kk) && (cle >= kk);
            unsigned ball = __ballot_sync(0xffffffffu, sel);
            kth = __shfl_sync(0xffffffffu, c, __ffs(ball) - 1);
        } else {
            // warp radix over candidates in shared
            unsigned prefix = 0u;
            for (int b = 30; b >= 0; --b) {
                unsigned t = prefix | (1u << b);
                int cc = 0;
                for (int idx = lane; idx < n; idx += 32) cc += (cand[idx] < t);
                #pragma unroll
                for (int off = 16; off; off >>= 1) cc += __shfl_xor_sync(0xffffffffu, cc, off);
                if (cc < kk) prefix = t;
            }
            kth = prefix;
        }
        if (lane == 0) sh_kth = kth;
    }
    __syncthreads();

    // ---- Histogram of neighbor labels: strict v < kth (exact bits) ----
    unsigned kth = sh_kth;
    #pragma unroll
    for (int s = 0; s < 32; ++s) {
        if (v[s] < kth) {
            int j = 4 * (tid + (s >> 2) * TPB_SEL) + (s & 3);
            atomicAdd(&counts[g_hard[j]], 1);
        }
    }
    __syncthreads();

    if (wid == 0) {
        float cnt = (lane < C) ? (float)counts[lane] : 0.f;
        float nn = cnt;
        #pragma unroll
        for (int off = 16; off; off >>= 1) nn += __shfl_xor_sync(0xffffffffu, nn, off);
        float ni = (nn > 1.f) ? nn : 1.f;
        float bfrac = cnt / ni;
        float h = -bfrac * logf(bfrac + 1e-5f);
        #pragma unroll
        for (int off = 16; off; off >>= 1) h += __shfl_xor_sync(0xffffffffu, h, off);
        if (lane == 0) out_ent[i] = h;
    }
}

// ---------------------------------------------------------------------------
__global__ void finalize_kernel(float* __restrict__ out2, int B, int C) {
    int lane = threadIdx.x;
    float g  = (lane < C) ? (float)g_gcounts[lane] : 0.f;
    float gb = g / (float)B;
    float h  = -gb * logf(gb + 1e-5f);
    float p  = (lane < C && g > 0.f) ? 1.f : 0.f;
    #pragma unroll
    for (int off = 16; off; off >>= 1) {
        h += __shfl_xor_sync(0xffffffffu, h, off);
        p += __shfl_xor_sync(0xffffffffu, p, off);
    }
    if (lane == 0) { out2[0] = h; out2[1] = p; }
}

// ---------------------------------------------------------------------------
// Output layout (flattened reference tuple):
//   [0, B*64)            encodings passthrough
//   [B*64, B*64+B)       neighbourhood_entropy
//   [B*64+B]             cluster_size_entropy
//   [B*64+B+1]           n_populated
//   [B*64+B+2, +B)       max_groups
// ---------------------------------------------------------------------------
extern "C" void kernel_launch(void* const* d_in, const int* in_sizes, int n_in,
                              void* d_out, int out_size) {
    const float* E    = (const float*)d_in[0];
    const float* Cat  = (const float*)d_in[1];
    const int*   kptr = (const int*)d_in[2];

    int B = in_sizes[0] / DIMS;
    int C = in_sizes[1] / B;

    float* out      = (float*)d_out;
    float* out_ent  = out + (size_t)B * DIMS;
    float* out_sc   = out_ent + B;
    float* out_maxg = out_sc + 2;

    cudaMemcpyAsync(out, E, (size_t)B * DIMS * sizeof(float),
                    cudaMemcpyDeviceToDevice, 0);

    zero_kernel<<<1, 64>>>();
    stats_kernel<<<(B * 32 + 255) / 256, 256>>>(E, Cat, out_maxg, B, C);
    gemm_kernel<<<dim3(B / 64, B / 64), 256>>>(E, B);
    select_kernel<<<B, TPB_SEL>>>(kptr, out_ent, B, C);
    finalize_kernel<<<1, 32>>>(out_sc, B, C);
}

// round 6
// speedup vs baseline: 2.4403x; 1.5145x over previous
#include <cuda_runtime.h>
#include <cuda_bf16.h>
#include <math.h>

#define DIMS 64
#define MAXB 8192
#define TPB_SEL 256
#define CAP 4096
#define KCAT 192        // [hi(64) | lo(64) | hi(64)] x [hi | hi | lo]

// Scratch (static device allocations are the sanctioned scratch mechanism).
static __device__ float g_d2[(size_t)MAXB * (size_t)MAXB];    // 256 MB
static __device__ float g_sq[MAXB];
static __device__ int   g_hard[MAXB];
static __device__ int   g_gcounts[64];
static __device__ __nv_bfloat16 g_Acat[(size_t)MAXB * KCAT];  // 3.1 MB
static __device__ __nv_bfloat16 g_Bcat[(size_t)MAXB * KCAT];  // 3.1 MB

// ---------------------------------------------------------------------------
__global__ void zero_kernel() {
    if (threadIdx.x < 64) g_gcounts[threadIdx.x] = 0;
}

// ---------------------------------------------------------------------------
// Split each fp32 value into bf16 hi+lo and build the concatenated operands:
//   dot(Acat_i, Bcat_j) = hi_i.hi_j + lo_i.hi_j + hi_i.lo_j  (= x.y - lo.lo)
// ---------------------------------------------------------------------------
__global__ void convert_kernel(const float* __restrict__ E, int B) {
    int idx = blockIdx.x * blockDim.x + threadIdx.x;
    if (idx >= B * DIMS) return;
    int i = idx >> 6, d = idx & 63;
    float x = E[idx];
    __nv_bfloat16 hi = __float2bfloat16(x);
    __nv_bfloat16 lo = __float2bfloat16(x - __bfloat162float(hi));
    size_t base = (size_t)i * KCAT;
    g_Acat[base + d]       = hi;
    g_Acat[base + 64 + d]  = lo;
    g_Acat[base + 128 + d] = hi;
    g_Bcat[base + d]       = hi;
    g_Bcat[base + 64 + d]  = hi;
    g_Bcat[base + 128 + d] = lo;
}

// ---------------------------------------------------------------------------
// Per-row: squared norm, argmax/max of categorical, global cluster counts.
// ---------------------------------------------------------------------------
__global__ void stats_kernel(const float* __restrict__ E,
                             const float* __restrict__ Cat,
                             float* __restrict__ out_maxg,
                             int B, int C) {
    int warp = (blockIdx.x * blockDim.x + threadIdx.x) >> 5;
    int lane = threadIdx.x & 31;
    if (warp >= B) return;

    float v0 = E[(size_t)warp * DIMS + lane];
    float v1 = E[(size_t)warp * DIMS + 32 + lane];
    float s = v0 * v0 + v1 * v1;
    #pragma unroll
    for (int off = 16; off; off >>= 1) s += __shfl_xor_sync(0xffffffffu, s, off);

    float mv = -INFINITY;
    int   mi = 0x7fffffff;
    for (int c = lane; c < C; c += 32) {
        float x = Cat[(size_t)warp * C + c];
        if (x > mv) { mv = x; mi = c; }
    }
    #pragma unroll
    for (int off = 16; off; off >>= 1) {
        float ov = __shfl_xor_sync(0xffffffffu, mv, off);
        int   oi = __shfl_xor_sync(0xffffffffu, mi, off);
        if (ov > mv || (ov == mv && oi < mi)) { mv = ov; mi = oi; }
    }

    if (lane == 0) {
        g_sq[warp]   = s;
        g_hard[warp] = mi;
        out_maxg[warp] = mv;
        atomicAdd(&g_gcounts[mi], 1);
    }
}

// ---------------------------------------------------------------------------
// Tensor-core GEMM (mma.sync m16n8k16 bf16 -> f32) producing g_d2 directly.
// Block tile 128x128, 8 warps as 4x2 (warp tile 32x64), K=192 in 3 chunks
// of 64 halves. Smem row stride 72 halves => conflict-free 32-bit fragment
// loads (bank = 4*g + t, all distinct).
// ---------------------------------------------------------------------------
__global__ void __launch_bounds__(256) mma_gemm_kernel(int B) {
    __shared__ __align__(16) __nv_bfloat16 Asm[128 * 72];
    __shared__ __align__(16) __nv_bfloat16 Bsm[128 * 72];

    int tid = threadIdx.x;
    int i0 = blockIdx.y * 128, j0 = blockIdx.x * 128;
    int wid = tid >> 5, lane = tid & 31;
    int m0 = (wid >> 1) * 32;     // warp_m in 0..3
    int n0 = (wid & 1) * 64;      // warp_n in 0..1
    int g = lane >> 2, t = lane & 3;

    float acc[2][8][4];
    #pragma unroll
    for (int mt = 0; mt < 2; ++mt)
        #pragma unroll
        for (int nt = 0; nt < 8; ++nt)
            #pragma unroll
            for (int r = 0; r < 4; ++r) acc[mt][nt][r] = 0.f;

    const uint4* gA = (const uint4*)g_Acat;   // 24 uint4 per row (192 halves)
    const uint4* gB = (const uint4*)g_Bcat;

    #pragma unroll
    for (int kc = 0; kc < 3; ++kc) {
        __syncthreads();
        #pragma unroll
        for (int q = 0; q < 4; ++q) {
            int idx = q * 256 + tid;          // 1024 uint4 per tile
            int r = idx >> 3, c = idx & 7;    // 8 uint4 per row-chunk
            *(uint4*)&Asm[r * 72 + c * 8] = gA[(size_t)(i0 + r) * 24 + kc * 8 + c];
            *(uint4*)&Bsm[r * 72 + c * 8] = gB[(size_t)(j0 + r) * 24 + kc * 8 + c];
        }
        __syncthreads();

        #pragma unroll
        for (int ks = 0; ks < 4; ++ks) {
            int k0 = ks * 16;
            unsigned a[2][4];
            #pragma unroll
            for (int mt = 0; mt < 2; ++mt) {
                int rm = m0 + mt * 16;
                a[mt][0] = *(const unsigned*)&Asm[(rm + g)     * 72 + k0 + t * 2];
                a[mt][1] = *(const unsigned*)&Asm[(rm + g + 8) * 72 + k0 + t * 2];
                a[mt][2] = *(const unsigned*)&Asm[(rm + g)     * 72 + k0 + t * 2 + 8];
                a[mt][3] = *(const unsigned*)&Asm[(rm + g + 8) * 72 + k0 + t * 2 + 8];
            }
            #pragma unroll
            for (int nt = 0; nt < 8; ++nt) {
                int jn = n0 + nt * 8;
                unsigned b0 = *(const unsigned*)&Bsm[(jn + g) * 72 + k0 + t * 2];
                unsigned b1 = *(const unsigned*)&Bsm[(jn + g) * 72 + k0 + t * 2 + 8];
                #pragma unroll
                for (int mt = 0; mt < 2; ++mt) {
                    asm volatile(
                        "mma.sync.aligned.m16n8k16.row.col.f32.bf16.bf16.f32 "
                        "{%0,%1,%2,%3}, {%4,%5,%6,%7}, {%8,%9}, {%0,%1,%2,%3};\n"
                        : "+f"(acc[mt][nt][0]), "+f"(acc[mt][nt][1]),
                          "+f"(acc[mt][nt][2]), "+f"(acc[mt][nt][3])
                        : "r"(a[mt][0]), "r"(a[mt][1]), "r"(a[mt][2]), "r"(a[mt][3]),
                          "r"(b0), "r"(b1));
                }
            }
        }
    }

    // Epilogue: d2 = sq_i + sq_j - 2*dot, clamp to +0, float2 stores.
    #pragma unroll
    for (int mt = 0; mt < 2; ++mt) {
        int ia = i0 + m0 + mt * 16 + g;
        float si0 = g_sq[ia], si1 = g_sq[ia + 8];
        #pragma unroll
        for (int nt = 0; nt < 8; ++nt) {
            int jc = j0 + n0 + nt * 8 + t * 2;
            float sj0 = g_sq[jc], sj1 = g_sq[jc + 1];
            float d00 = si0 + sj0 - 2.f * acc[mt][nt][0]; d00 = d00 > 0.f ? d00 : 0.f;
            float d01 = si0 + sj1 - 2.f * acc[mt][nt][1]; d01 = d01 > 0.f ? d01 : 0.f;
            float d10 = si1 + sj0 - 2.f * acc[mt][nt][2]; d10 = d10 > 0.f ? d10 : 0.f;
            float d11 = si1 + sj1 - 2.f * acc[mt][nt][3]; d11 = d11 > 0.f ? d11 : 0.f;
            *(float2*)(g_d2 + (size_t)ia * B + jc)       = make_float2(d00, d01);
            *(float2*)(g_d2 + (size_t)(ia + 8) * B + jc) = make_float2(d10, d11);
        }
    }
}

// ---------------------------------------------------------------------------
// Per-row selection + neighborhood entropy (unchanged from R5; DRAM-leaning).
// ---------------------------------------------------------------------------
__global__ void __launch_bounds__(TPB_SEL) select_kernel(const int* __restrict__ kptr,
                                                         float* __restrict__ out_ent,
                                                         int B, int C) {
    int i    = blockIdx.x;
    int tid  = threadIdx.x;
    int lane = tid & 31;
    int wid  = tid >> 5;

    int k = *kptr;
    if (k > B / 4) k = B / 4;
    int kk = k + 1;

    __shared__ unsigned sm_min[TPB_SEL];
    __shared__ unsigned cand[CAP];
    __shared__ int      ncand;
    __shared__ unsigned sh_tub, sh_kth;
    __shared__ int      counts[64];
    __shared__ int      sred[8];

    const uint4* row4 = (const uint4*)(g_d2 + (size_t)i * B);
    unsigned v[32];
    unsigned mn = 0xffffffffu;
    #pragma unroll
    for (int s = 0; s < 8; ++s) {
        uint4 q = row4[tid + s * TPB_SEL];
        v[4 * s + 0] = q.x; v[4 * s + 1] = q.y;
        v[4 * s + 2] = q.z; v[4 * s + 3] = q.w;
        unsigned m01 = min(q.x, q.y), m23 = min(q.z, q.w);
        mn = min(mn, min(m01, m23));
    }
    sm_min[tid] = mn;
    if (tid < 64) counts[tid] = 0;
    if (tid == 0) ncand = 0;
    __syncthreads();

    if (wid == 0) {
        unsigned tub;
        if (kk <= 32) {
            unsigned m = sm_min[lane];
            #pragma unroll
            for (int s = 1; s < 8; ++s) m = min(m, sm_min[lane + 32 * s]);
            int cls = 0, cle = 0;
            #pragma unroll
            for (int j = 0; j < 32; ++j) {
                unsigned b = __shfl_sync(0xffffffffu, m, j);
                cls += (b < m);
                cle += (b <= m);
            }
            bool sel = (cls < kk) && (cle >= kk);
            unsigned ball = __ballot_sync(0xffffffffu, sel);
            tub = __shfl_sync(0xffffffffu, m, __ffs(ball) - 1);
        } else {
            tub = 0xffffffffu;
        }
        if (lane == 0) sh_tub = tub;
    }
    __syncthreads();

    unsigned tub = sh_tub;
    bool fullscan = (tub == 0xffffffffu);
    if (!fullscan) {
        #pragma unroll
        for (int s = 0; s < 32; ++s) {
            if (v[s] <= tub) {
                int p = atomicAdd(&ncand, 1);
                if (p < CAP) cand[p] = v[s];
            }
        }
    }
    __syncthreads();

    int n = ncand;
    if (fullscan || n > CAP) {
        unsigned prefix = 0u;
        for (int b = 30; b >= 0; --b) {
            unsigned tcand = prefix | (1u << b);
            int c = 0;
            #pragma unroll
            for (int s = 0; s < 32; ++s) c += (v[s] < tcand);
            #pragma unroll
            for (int off = 16; off; off >>= 1) c += __shfl_xor_sync(0xffffffffu, c, off);
            if (lane == 0) sred[wid] = c;
            __syncthreads();
            int tot = sred[0] + sred[1] + sred[2] + sred[3] +
                      sred[4] + sred[5] + sred[6] + sred[7];
            if (tot < kk) prefix = tcand;
            __syncthreads();
        }
        if (tid == 0) sh_kth = prefix;
    } else if (wid == 0) {
        unsigned kth;
        if (n <= 32) {
            unsigned c = (lane < n) ? cand[lane] : 0xffffffffu;
            int cls = 0, cle = 0;
            for (int j = 0; j < n; ++j) {
                unsigned b = __shfl_sync(0xffffffffu, c, j);
                cls += (b < c);
                cle += (b <= c);
            }
            bool sel = (cls < kk) && (cle >= kk);
            unsigned ball = __ballot_sync(0xffffffffu, sel);
            kth = __shfl_sync(0xffffffffu, c, __ffs(ball) - 1);
        } else {
            unsigned prefix = 0u;
            for (int b = 30; b >= 0; --b) {
                unsigned tcand = prefix | (1u << b);
                int cc = 0;
                for (int idx = lane; idx < n; idx += 32) cc += (cand[idx] < tcand);
                #pragma unroll
                for (int off = 16; off; off >>= 1) cc += __shfl_xor_sync(0xffffffffu, cc, off);
                if (cc < kk) prefix = tcand;
            }
            kth = prefix;
        }
        if (lane == 0) sh_kth = kth;
    }
    __syncthreads();

    unsigned kth = sh_kth;
    #pragma unroll
    for (int s = 0; s < 32; ++s) {
        if (v[s] < kth) {
            int j = 4 * (tid + (s >> 2) * TPB_SEL) + (s & 3);
            atomicAdd(&counts[g_hard[j]], 1);
        }
    }
    __syncthreads();

    if (wid == 0) {
        float cnt = (lane < C) ? (float)counts[lane] : 0.f;
        float nn = cnt;
        #pragma unroll
        for (int off = 16; off; off >>= 1) nn += __shfl_xor_sync(0xffffffffu, nn, off);
        float ni = (nn > 1.f) ? nn : 1.f;
        float bfrac = cnt / ni;
        float h = -bfrac * logf(bfrac + 1e-5f);
        #pragma unroll
        for (int off = 16; off; off >>= 1) h += __shfl_xor_sync(0xffffffffu, h, off);
        if (lane == 0) out_ent[i] = h;
    }
}

// ---------------------------------------------------------------------------
__global__ void finalize_kernel(float* __restrict__ out2, int B, int C) {
    int lane = threadIdx.x;
    float g  = (lane < C) ? (float)g_gcounts[lane] : 0.f;
    float gb = g / (float)B;
    float h  = -gb * logf(gb + 1e-5f);
    float p  = (lane < C && g > 0.f) ? 1.f : 0.f;
    #pragma unroll
    for (int off = 16; off; off >>= 1) {
        h += __shfl_xor_sync(0xffffffffu, h, off);
        p += __shfl_xor_sync(0xffffffffu, p, off);
    }
    if (lane == 0) { out2[0] = h; out2[1] = p; }
}

// ---------------------------------------------------------------------------
// Output layout (flattened reference tuple):
//   [0, B*64)            encodings passthrough
//   [B*64, B*64+B)       neighbourhood_entropy
//   [B*64+B]             cluster_size_entropy
//   [B*64+B+1]           n_populated
//   [B*64+B+2, +B)       max_groups
// ---------------------------------------------------------------------------
extern "C" void kernel_launch(void* const* d_in, const int* in_sizes, int n_in,
                              void* d_out, int out_size) {
    const float* E    = (const float*)d_in[0];
    const float* Cat  = (const float*)d_in[1];
    const int*   kptr = (const int*)d_in[2];

    int B = in_sizes[0] / DIMS;
    int C = in_sizes[1] / B;

    float* out      = (float*)d_out;
    float* out_ent  = out + (size_t)B * DIMS;
    float* out_sc   = out_ent + B;
    float* out_maxg = out_sc + 2;

    cudaMemcpyAsync(out, E, (size_t)B * DIMS * sizeof(float),
                    cudaMemcpyDeviceToDevice, 0);

    zero_kernel<<<1, 64>>>();
    convert_kernel<<<(B * DIMS + 255) / 256, 256>>>(E, B);
    stats_kernel<<<(B * 32 + 255) / 256, 256>>>(E, Cat, out_maxg, B, C);
    mma_gemm_kernel<<<dim3(B / 128, B / 128), 256>>>(B);
    select_kernel<<<B, TPB_SEL>>>(kptr, out_ent, B, C);
    finalize_kernel<<<1, 32>>>(out_sc, B, C);
}

// round 7
// speedup vs baseline: 2.8814x; 1.1807x over previous
#include <cuda_runtime.h>
#include <cuda_bf16.h>
#include <math.h>

#define DIMS 64
#define MAXB 8192
#define TPB_SEL 256
#define CAP 4096
#define KCAT 192        // [hi(64) | lo(64) | hi(64)] x [hi | hi | lo]
#define SSTR 200        // smem row stride in halves (400B: LDSM conflict-free)
#define SMEM_BYTES (2 * 128 * SSTR * 2)   // A + B tiles, 102400 B

// Scratch (static device allocations are the sanctioned scratch mechanism).
static __device__ float g_d2[(size_t)MAXB * (size_t)MAXB];    // 256 MB
static __device__ float g_sq[MAXB];
static __device__ int   g_hard[MAXB];
static __device__ int   g_gcounts[64];
static __device__ __nv_bfloat16 g_Acat[(size_t)MAXB * KCAT];  // 3.1 MB
static __device__ __nv_bfloat16 g_Bcat[(size_t)MAXB * KCAT];  // 3.1 MB

// ---------------------------------------------------------------------------
__global__ void zero_kernel() {
    if (threadIdx.x < 64) g_gcounts[threadIdx.x] = 0;
}

// ---------------------------------------------------------------------------
// Split fp32 -> bf16 hi+lo, build concatenated operands:
//   dot(Acat_i, Bcat_j) = hi.hi + lo.hi + hi.lo  (= x.y - lo.lo, |lo.lo|~1e-7)
// ---------------------------------------------------------------------------
__global__ void convert_kernel(const float* __restrict__ E, int B) {
    int idx = blockIdx.x * blockDim.x + threadIdx.x;
    if (idx >= B * DIMS) return;
    int i = idx >> 6, d = idx & 63;
    float x = E[idx];
    __nv_bfloat16 hi = __float2bfloat16(x);
    __nv_bfloat16 lo = __float2bfloat16(x - __bfloat162float(hi));
    size_t base = (size_t)i * KCAT;
    g_Acat[base + d]       = hi;
    g_Acat[base + 64 + d]  = lo;
    g_Acat[base + 128 + d] = hi;
    g_Bcat[base + d]       = hi;
    g_Bcat[base + 64 + d]  = hi;
    g_Bcat[base + 128 + d] = lo;
}

// ---------------------------------------------------------------------------
// Per-row: squared norm, argmax/max of categorical, global cluster counts.
// ---------------------------------------------------------------------------
__global__ void stats_kernel(const float* __restrict__ E,
                             const float* __restrict__ Cat,
                             float* __restrict__ out_maxg,
                             int B, int C) {
    int warp = (blockIdx.x * blockDim.x + threadIdx.x) >> 5;
    int lane = threadIdx.x & 31;
    if (warp >= B) return;

    float v0 = E[(size_t)warp * DIMS + lane];
    float v1 = E[(size_t)warp * DIMS + 32 + lane];
    float s = v0 * v0 + v1 * v1;
    #pragma unroll
    for (int off = 16; off; off >>= 1) s += __shfl_xor_sync(0xffffffffu, s, off);

    float mv = -INFINITY;
    int   mi = 0x7fffffff;
    for (int c = lane; c < C; c += 32) {
        float x = Cat[(size_t)warp * C + c];
        if (x > mv) { mv = x; mi = c; }
    }
    #pragma unroll
    for (int off = 16; off; off >>= 1) {
        float ov = __shfl_xor_sync(0xffffffffu, mv, off);
        int   oi = __shfl_xor_sync(0xffffffffu, mi, off);
        if (ov > mv || (ov == mv && oi < mi)) { mv = ov; mi = oi; }
    }

    if (lane == 0) {
        g_sq[warp]   = s;
        g_hard[warp] = mi;
        out_maxg[warp] = mv;
        atomicAdd(&g_gcounts[mi], 1);
    }
}

// ---------------------------------------------------------------------------
__device__ __forceinline__ void ldsm_x4(unsigned& r0, unsigned& r1,
                                        unsigned& r2, unsigned& r3, unsigned a) {
    asm volatile("ldmatrix.sync.aligned.m8n8.x4.shared.b16 {%0,%1,%2,%3}, [%4];"
                 : "=r"(r0), "=r"(r1), "=r"(r2), "=r"(r3) : "r"(a));
}
__device__ __forceinline__ void cp16(unsigned saddr, const void* gaddr) {
    asm volatile("cp.async.cg.shared.global [%0], [%1], 16;"
                 :: "r"(saddr), "l"(gaddr));
}

// ---------------------------------------------------------------------------
// Tensor-core GEMM: block tile 128x128, 8 warps (4x2), full K=192 resident
// in dynamic smem (cp.async), ldmatrix fragment feeds, 2 CTAs/SM.
// ---------------------------------------------------------------------------
__global__ void __launch_bounds__(256, 2) mma_gemm_kernel(int B) {
    extern __shared__ __align__(16) __nv_bfloat16 smem[];
    const unsigned A_OFF = 0;
    const unsigned B_OFF = 128 * SSTR * 2;   // bytes

    int tid = threadIdx.x;
    int i0 = blockIdx.y * 128, j0 = blockIdx.x * 128;
    int wid = tid >> 5, lane = tid & 31;
    int m0 = (wid >> 1) * 32;     // warp_m: 0..3
    int n0 = (wid & 1) * 64;      // warp_n: 0..1

    unsigned sbase;
    asm("{ .reg .u64 t; cvta.to.shared.u64 t, %1; cvt.u32.u64 %0, t; }"
        : "=r"(sbase) : "l"(smem));
    unsigned sA = sbase + A_OFF, sB = sbase + B_OFF;

    // ---- load full K panel for both tiles via cp.async ----
    const char* gA = (const char*)g_Acat;
    const char* gB = (const char*)g_Bcat;
    #pragma unroll
    for (int it = 0; it < 12; ++it) {
        int idx = it * 256 + tid;         // 3072 16B-chunks per tile
        int r = idx / 24, c = idx % 24;   // 24 x 16B per 384B row
        cp16(sA + r * (SSTR * 2) + c * 16, gA + (size_t)(i0 + r) * 384 + c * 16);
        cp16(sB + r * (SSTR * 2) + c * 16, gB + (size_t)(j0 + r) * 384 + c * 16);
    }
    asm volatile("cp.async.commit_group;");
    asm volatile("cp.async.wait_group 0;");
    __syncthreads();

    float acc[2][8][4];
    #pragma unroll
    for (int mt = 0; mt < 2; ++mt)
        #pragma unroll
        for (int nt = 0; nt < 8; ++nt)
            #pragma unroll
            for (int r = 0; r < 4; ++r) acc[mt][nt][r] = 0.f;

    // per-lane invariant ldmatrix base addresses
    unsigned aab = sA + (unsigned)(m0 + (lane & 15)) * (SSTR * 2)
                 + ((lane >> 4) * 16);
    unsigned bab = sB + (unsigned)(n0 + (lane & 7) + ((lane >> 4) << 3)) * (SSTR * 2)
                 + (((lane >> 3) & 1) * 16);

    #pragma unroll
    for (int ks = 0; ks < 12; ++ks) {       // K = 192 = 12 x 16
        unsigned kb = ks * 32;              // 16 halves = 32 bytes
        unsigned a0[4], a1[4];
        ldsm_x4(a0[0], a0[1], a0[2], a0[3], aab + kb);                    // rows m0..m0+15
        ldsm_x4(a1[0], a1[1], a1[2], a1[3], aab + kb + 16 * (SSTR * 2)); // rows +16..+31
        #pragma unroll
        for (int p = 0; p < 4; ++p) {       // 4 x (two n8 tiles)
            unsigned b0, b1, b2, b3;
            ldsm_x4(b0, b1, b2, b3, bab + kb + (unsigned)p * 16 * (SSTR * 2));
            asm volatile(
                "mma.sync.aligned.m16n8k16.row.col.f32.bf16.bf16.f32 "
                "{%0,%1,%2,%3}, {%4,%5,%6,%7}, {%8,%9}, {%0,%1,%2,%3};\n"
                : "+f"(acc[0][2*p][0]), "+f"(acc[0][2*p][1]),
                  "+f"(acc[0][2*p][2]), "+f"(acc[0][2*p][3])
                : "r"(a0[0]), "r"(a0[1]), "r"(a0[2]), "r"(a0[3]), "r"(b0), "r"(b1));
            asm volatile(
                "mma.sync.aligned.m16n8k16.row.col.f32.bf16.bf16.f32 "
                "{%0,%1,%2,%3}, {%4,%5,%6,%7}, {%8,%9}, {%0,%1,%2,%3};\n"
                : "+f"(acc[0][2*p+1][0]), "+f"(acc[0][2*p+1][1]),
                  "+f"(acc[0][2*p+1][2]), "+f"(acc[0][2*p+1][3])
                : "r"(a0[0]), "r"(a0[1]), "r"(a0[2]), "r"(a0[3]), "r"(b2), "r"(b3));
            asm volatile(
                "mma.sync.aligned.m16n8k16.row.col.f32.bf16.bf16.f32 "
                "{%0,%1,%2,%3}, {%4,%5,%6,%7}, {%8,%9}, {%0,%1,%2,%3};\n"
                : "+f"(acc[1][2*p][0]), "+f"(acc[1][2*p][1]),
                  "+f"(acc[1][2*p][2]), "+f"(acc[1][2*p][3])
                : "r"(a1[0]), "r"(a1[1]), "r"(a1[2]), "r"(a1[3]), "r"(b0), "r"(b1));
            asm volatile(
                "mma.sync.aligned.m16n8k16.row.col.f32.bf16.bf16.f32 "
                "{%0,%1,%2,%3}, {%4,%5,%6,%7}, {%8,%9}, {%0,%1,%2,%3};\n"
                : "+f"(acc[1][2*p+1][0]), "+f"(acc[1][2*p+1][1]),
                  "+f"(acc[1][2*p+1][2]), "+f"(acc[1][2*p+1][3])
                : "r"(a1[0]), "r"(a1[1]), "r"(a1[2]), "r"(a1[3]), "r"(b2), "r"(b3));
        }
    }

    // Epilogue: d2 = sq_i + sq_j - 2*dot, clamp to +0, float2 stores.
    int g = lane >> 2, t = lane & 3;
    #pragma unroll
    for (int mt = 0; mt < 2; ++mt) {
        int ia = i0 + m0 + mt * 16 + g;
        float si0 = g_sq[ia], si1 = g_sq[ia + 8];
        #pragma unroll
        for (int nt = 0; nt < 8; ++nt) {
            int jc = j0 + n0 + nt * 8 + t * 2;
            float sj0 = g_sq[jc], sj1 = g_sq[jc + 1];
            float d00 = si0 + sj0 - 2.f * acc[mt][nt][0]; d00 = d00 > 0.f ? d00 : 0.f;
            float d01 = si0 + sj1 - 2.f * acc[mt][nt][1]; d01 = d01 > 0.f ? d01 : 0.f;
            float d10 = si1 + sj0 - 2.f * acc[mt][nt][2]; d10 = d10 > 0.f ? d10 : 0.f;
            float d11 = si1 + sj1 - 2.f * acc[mt][nt][3]; d11 = d11 > 0.f ? d11 : 0.f;
            *(float2*)(g_d2 + (size_t)ia * B + jc)       = make_float2(d00, d01);
            *(float2*)(g_d2 + (size_t)(ia + 8) * B + jc) = make_float2(d10, d11);
        }
    }
}

// ---------------------------------------------------------------------------
// Per-row selection + neighborhood entropy (R5 pruned scheme, DRAM-leaning).
// ---------------------------------------------------------------------------
__global__ void __launch_bounds__(TPB_SEL) select_kernel(const int* __restrict__ kptr,
                                                         float* __restrict__ out_ent,
                                                         int B, int C) {
    int i    = blockIdx.x;
    int tid  = threadIdx.x;
    int lane = tid & 31;
    int wid  = tid >> 5;

    int k = *kptr;
    if (k > B / 4) k = B / 4;
    int kk = k + 1;

    __shared__ unsigned sm_min[TPB_SEL];
    __shared__ unsigned cand[CAP];
    __shared__ int      ncand;
    __shared__ unsigned sh_tub, sh_kth;
    __shared__ int      counts[64];
    __shared__ int      sred[8];

    const uint4* row4 = (const uint4*)(g_d2 + (size_t)i * B);
    unsigned v[32];
    unsigned mn = 0xffffffffu;
    #pragma unroll
    for (int s = 0; s < 8; ++s) {
        uint4 q = row4[tid + s * TPB_SEL];
        v[4 * s + 0] = q.x; v[4 * s + 1] = q.y;
        v[4 * s + 2] = q.z; v[4 * s + 3] = q.w;
        unsigned m01 = min(q.x, q.y), m23 = min(q.z, q.w);
        mn = min(mn, min(m01, m23));
    }
    sm_min[tid] = mn;
    if (tid < 64) counts[tid] = 0;
    if (tid == 0) ncand = 0;
    __syncthreads();

    if (wid == 0) {
        unsigned tub;
        if (kk <= 32) {
            unsigned m = sm_min[lane];
            #pragma unroll
            for (int s = 1; s < 8; ++s) m = min(m, sm_min[lane + 32 * s]);
            int cls = 0, cle = 0;
            #pragma unroll
            for (int j = 0; j < 32; ++j) {
                unsigned b = __shfl_sync(0xffffffffu, m, j);
                cls += (b < m);
                cle += (b <= m);
            }
            bool sel = (cls < kk) && (cle >= kk);
            unsigned ball = __ballot_sync(0xffffffffu, sel);
            tub = __shfl_sync(0xffffffffu, m, __ffs(ball) - 1);
        } else {
            tub = 0xffffffffu;
        }
        if (lane == 0) sh_tub = tub;
    }
    __syncthreads();

    unsigned tub = sh_tub;
    bool fullscan = (tub == 0xffffffffu);
    if (!fullscan) {
        #pragma unroll
        for (int s = 0; s < 32; ++s) {
            if (v[s] <= tub) {
                int p = atomicAdd(&ncand, 1);
                if (p < CAP) cand[p] = v[s];
            }
        }
    }
    __syncthreads();

    int n = ncand;
    if (fullscan || n > CAP) {
        unsigned prefix = 0u;
        for (int b = 30; b >= 0; --b) {
            unsigned tcand = prefix | (1u << b);
            int c = 0;
            #pragma unroll
            for (int s = 0; s < 32; ++s) c += (v[s] < tcand);
            #pragma unroll
            for (int off = 16; off; off >>= 1) c += __shfl_xor_sync(0xffffffffu, c, off);
            if (lane == 0) sred[wid] = c;
            __syncthreads();
            int tot = sred[0] + sred[1] + sred[2] + sred[3] +
                      sred[4] + sred[5] + sred[6] + sred[7];
            if (tot < kk) prefix = tcand;
            __syncthreads();
        }
        if (tid == 0) sh_kth = prefix;
    } else if (wid == 0) {
        unsigned kth;
        if (n <= 32) {
            unsigned c = (lane < n) ? cand[lane] : 0xffffffffu;
            int cls = 0, cle = 0;
            for (int j = 0; j < n; ++j) {
                unsigned b = __shfl_sync(0xffffffffu, c, j);
                cls += (b < c);
                cle += (b <= c);
            }
            bool sel = (cls < kk) && (cle >= kk);
            unsigned ball = __ballot_sync(0xffffffffu, sel);
            kth = __shfl_sync(0xffffffffu, c, __ffs(ball) - 1);
        } else {
            unsigned prefix = 0u;
            for (int b = 30; b >= 0; --b) {
                unsigned tcand = prefix | (1u << b);
                int cc = 0;
                for (int idx = lane; idx < n; idx += 32) cc += (cand[idx] < tcand);
                #pragma unroll
                for (int off = 16; off; off >>= 1) cc += __shfl_xor_sync(0xffffffffu, cc, off);
                if (cc < kk) prefix = tcand;
            }
            kth = prefix;
        }
        if (lane == 0) sh_kth = kth;
    }
    __syncthreads();

    unsigned kth = sh_kth;
    #pragma unroll
    for (int s = 0; s < 32; ++s) {
        if (v[s] < kth) {
            int j = 4 * (tid + (s >> 2) * TPB_SEL) + (s & 3);
            atomicAdd(&counts[g_hard[j]], 1);
        }
    }
    __syncthreads();

    if (wid == 0) {
        float cnt = (lane < C) ? (float)counts[lane] : 0.f;
        float nn = cnt;
        #pragma unroll
        for (int off = 16; off; off >>= 1) nn += __shfl_xor_sync(0xffffffffu, nn, off);
        float ni = (nn > 1.f) ? nn : 1.f;
        float bfrac = cnt / ni;
        float h = -bfrac * logf(bfrac + 1e-5f);
        #pragma unroll
        for (int off = 16; off; off >>= 1) h += __shfl_xor_sync(0xffffffffu, h, off);
        if (lane == 0) out_ent[i] = h;
    }
}

// ---------------------------------------------------------------------------
__global__ void finalize_kernel(float* __restrict__ out2, int B, int C) {
    int lane = threadIdx.x;
    float g  = (lane < C) ? (float)g_gcounts[lane] : 0.f;
    float gb = g / (float)B;
    float h  = -gb * logf(gb + 1e-5f);
    float p  = (lane < C && g > 0.f) ? 1.f : 0.f;
    #pragma unroll
    for (int off = 16; off; off >>= 1) {
        h += __shfl_xor_sync(0xffffffffu, h, off);
        p += __shfl_xor_sync(0xffffffffu, p, off);
    }
    if (lane == 0) { out2[0] = h; out2[1] = p; }
}

// ---------------------------------------------------------------------------
// Output layout (flattened reference tuple):
//   [0, B*64)            encodings passthrough
//   [B*64, B*64+B)       neighbourhood_entropy
//   [B*64+B]             cluster_size_entropy
//   [B*64+B+1]           n_populated
//   [B*64+B+2, +B)       max_groups
// ---------------------------------------------------------------------------
extern "C" void kernel_launch(void* const* d_in, const int* in_sizes, int n_in,
                              void* d_out, int out_size) {
    const float* E    = (const float*)d_in[0];
    const float* Cat  = (const float*)d_in[1];
    const int*   kptr = (const int*)d_in[2];

    int B = in_sizes[0] / DIMS;
    int C = in_sizes[1] / B;

    float* out      = (float*)d_out;
    float* out_ent  = out + (size_t)B * DIMS;
    float* out_sc   = out_ent + B;
    float* out_maxg = out_sc + 2;

    cudaMemcpyAsync(out, E, (size_t)B * DIMS * sizeof(float),
                    cudaMemcpyDeviceToDevice, 0);

    cudaFuncSetAttribute(mma_gemm_kernel,
                         cudaFuncAttributeMaxDynamicSharedMemorySize, SMEM_BYTES);

    zero_kernel<<<1, 64>>>();
    convert_kernel<<<(B * DIMS + 255) / 256, 256>>>(E, B);
    stats_kernel<<<(B * 32 + 255) / 256, 256>>>(E, Cat, out_maxg, B, C);
    mma_gemm_kernel<<<dim3(B / 128, B / 128), 256, SMEM_BYTES>>>(B);
    select_kernel<<<B, TPB_SEL>>>(kptr, out_ent, B, C);
    finalize_kernel<<<1, 32>>>(out_sc, B, C);
}

// round 8
// speedup vs baseline: 3.7186x; 1.2906x over previous
#include <cuda_runtime.h>
#include <cuda_bf16.h>
#include <math.h>

#define DIMS 64
#define MAXB 8192
#define TPB_SEL 256
#define CAP 4096
#define KCAT 192          // [hi(64) | lo(64) | hi(64)] x [hi | hi | lo]
#define CH_BYTES 18432    // 128 rows x 144B per tile-chunk
#define SMEM_BYTES (2 * 2 * CH_BYTES)   // 2 buffers x (A + B) = 73728 B

// Scratch (static device allocations are the sanctioned scratch mechanism).
static __device__ float g_d2[(size_t)MAXB * (size_t)MAXB];    // 256 MB
static __device__ float g_sq[MAXB];
static __device__ int   g_hard[MAXB];
static __device__ int   g_gcounts[64];
static __device__ __nv_bfloat16 g_Acat[(size_t)MAXB * KCAT];  // 3.1 MB
static __device__ __nv_bfloat16 g_Bcat[(size_t)MAXB * KCAT];  // 3.1 MB

// ---------------------------------------------------------------------------
__global__ void zero_kernel() {
    if (threadIdx.x < 64) g_gcounts[threadIdx.x] = 0;
}

// ---------------------------------------------------------------------------
// Split fp32 -> bf16 hi+lo, build concatenated operands:
//   dot(Acat_i, Bcat_j) = hi.hi + lo.hi + hi.lo  (= x.y - lo.lo, |lo.lo|~1e-7)
// ---------------------------------------------------------------------------
__global__ void convert_kernel(const float* __restrict__ E, int B) {
    int idx = blockIdx.x * blockDim.x + threadIdx.x;
    if (idx >= B * DIMS) return;
    int i = idx >> 6, d = idx & 63;
    float x = E[idx];
    __nv_bfloat16 hi = __float2bfloat16(x);
    __nv_bfloat16 lo = __float2bfloat16(x - __bfloat162float(hi));
    size_t base = (size_t)i * KCAT;
    g_Acat[base + d]       = hi;
    g_Acat[base + 64 + d]  = lo;
    g_Acat[base + 128 + d] = hi;
    g_Bcat[base + d]       = hi;
    g_Bcat[base + 64 + d]  = hi;
    g_Bcat[base + 128 + d] = lo;
}

// ---------------------------------------------------------------------------
// Per-row: squared norm, argmax/max of categorical, global cluster counts.
// ---------------------------------------------------------------------------
__global__ void stats_kernel(const float* __restrict__ E,
                             const float* __restrict__ Cat,
                             float* __restrict__ out_maxg,
                             int B, int C) {
    int warp = (blockIdx.x * blockDim.x + threadIdx.x) >> 5;
    int lane = threadIdx.x & 31;
    if (warp >= B) return;

    float v0 = E[(size_t)warp * DIMS + lane];
    float v1 = E[(size_t)warp * DIMS + 32 + lane];
    float s = v0 * v0 + v1 * v1;
    #pragma unroll
    for (int off = 16; off; off >>= 1) s += __shfl_xor_sync(0xffffffffu, s, off);

    float mv = -INFINITY;
    int   mi = 0x7fffffff;
    for (int c = lane; c < C; c += 32) {
        float x = Cat[(size_t)warp * C + c];
        if (x > mv) { mv = x; mi = c; }
    }
    #pragma unroll
    for (int off = 16; off; off >>= 1) {
        float ov = __shfl_xor_sync(0xffffffffu, mv, off);
        int   oi = __shfl_xor_sync(0xffffffffu, mi, off);
        if (ov > mv || (ov == mv && oi < mi)) { mv = ov; mi = oi; }
    }

    if (lane == 0) {
        g_sq[warp]   = s;
        g_hard[warp] = mi;
        out_maxg[warp] = mv;
        atomicAdd(&g_gcounts[mi], 1);
    }
}

// ---------------------------------------------------------------------------
__device__ __forceinline__ void ldsm_x4(unsigned& r0, unsigned& r1,
                                        unsigned& r2, unsigned& r3, unsigned a) {
    asm volatile("ldmatrix.sync.aligned.m8n8.x4.shared.b16 {%0,%1,%2,%3}, [%4];"
                 : "=r"(r0), "=r"(r1), "=r"(r2), "=r"(r3) : "r"(a));
}
__device__ __forceinline__ void cp16(unsigned saddr, const void* gaddr) {
    asm volatile("cp.async.cg.shared.global [%0], [%1], 16;"
                 :: "r"(saddr), "l"(gaddr));
}
#define MMA_BF16(ACC, A, B0, B1)                                             \
    asm volatile(                                                            \
        "mma.sync.aligned.m16n8k16.row.col.f32.bf16.bf16.f32 "               \
        "{%0,%1,%2,%3}, {%4,%5,%6,%7}, {%8,%9}, {%0,%1,%2,%3};\n"            \
        : "+f"((ACC)[0]), "+f"((ACC)[1]), "+f"((ACC)[2]), "+f"((ACC)[3])     \
        : "r"((A)[0]), "r"((A)[1]), "r"((A)[2]), "r"((A)[3]),                \
          "r"(B0), "r"(B1))

// ---------------------------------------------------------------------------
// Symmetric tensor-core GEMM (triangle-only grid) with double-buffered
// cp.async K-chunk pipeline. Block tile 128x128, 8 warps (4x2 of 32x64),
// K=192 in 3 chunks of 64 halves (stride 144B: LDSM conflict-free).
// Off-diagonal blocks write their tile straight AND transposed.
// ---------------------------------------------------------------------------
__global__ void __launch_bounds__(256, 2) mma_gemm_kernel(int B) {
    extern __shared__ __align__(16) char smem[];

    // triangular decode: block x -> (bi >= bj)
    int x = blockIdx.x;
    int bi = (int)((sqrtf(8.0f * (float)x + 1.0f) - 1.0f) * 0.5f);
    while ((bi + 1) * (bi + 2) / 2 <= x) ++bi;
    while (bi * (bi + 1) / 2 > x) --bi;
    int bj = x - bi * (bi + 1) / 2;
    int i0 = bi * 128, j0 = bj * 128;

    int tid = threadIdx.x;
    int wid = tid >> 5, lane = tid & 31;
    int m0 = (wid >> 1) * 32;     // warp_m: 0..3
    int n0 = (wid & 1) * 64;      // warp_n: 0..1

    unsigned sbase;
    asm("{ .reg .u64 t; cvta.to.shared.u64 t, %1; cvt.u32.u64 %0, t; }"
        : "=r"(sbase) : "l"(smem));
    // buffer b: A at sbase + b*2*CH, B at +CH
    const char* gA = (const char*)g_Acat;
    const char* gB = (const char*)g_Bcat;

    // per-lane ldmatrix offsets (within a tile-chunk)
    unsigned aoff = (unsigned)(m0 + (lane & 15)) * 144 + ((lane >> 4) * 16);
    unsigned boff = (unsigned)(n0 + (lane & 7) + ((lane >> 4) << 3)) * 144
                  + (((lane >> 3) & 1) * 16);

    float acc[2][8][4];
    #pragma unroll
    for (int mt = 0; mt < 2; ++mt)
        #pragma unroll
        for (int nt = 0; nt < 8; ++nt)
            #pragma unroll
            for (int r = 0; r < 4; ++r) acc[mt][nt][r] = 0.f;

    // ---- load chunk kc into buffer kc&1 ----
    auto load_chunk = [&](int kc) {
        unsigned sA = sbase + (unsigned)(kc & 1) * (2 * CH_BYTES);
        unsigned sB = sA + CH_BYTES;
        #pragma unroll
        for (int it = 0; it < 4; ++it) {
            int idx = it * 256 + tid;          // 1024 16B-chunks per tile
            int r = idx >> 3, c = idx & 7;
            cp16(sA + r * 144 + c * 16, gA + (size_t)(i0 + r) * 384 + kc * 128 + c * 16);
            cp16(sB + r * 144 + c * 16, gB + (size_t)(j0 + r) * 384 + kc * 128 + c * 16);
        }
        asm volatile("cp.async.commit_group;");
    };

    load_chunk(0);
    load_chunk(1);

    #pragma unroll
    for (int kc = 0; kc < 3; ++kc) {
        if (kc < 2) asm volatile("cp.async.wait_group 1;");
        else        asm volatile("cp.async.wait_group 0;");
        __syncthreads();

        unsigned sA = sbase + (unsigned)(kc & 1) * (2 * CH_BYTES);
        unsigned sB = sA + CH_BYTES;
        unsigned aab = sA + aoff, bab = sB + boff;

        #pragma unroll
        for (int ks = 0; ks < 4; ++ks) {       // 64 halves = 4 x 16
            unsigned kb = ks * 32;
            unsigned a0[4], a1[4];
            ldsm_x4(a0[0], a0[1], a0[2], a0[3], aab + kb);
            ldsm_x4(a1[0], a1[1], a1[2], a1[3], aab + kb + 16 * 144);
            #pragma unroll
            for (int p = 0; p < 4; ++p) {
                unsigned b0, b1, b2, b3;
                ldsm_x4(b0, b1, b2, b3, bab + kb + (unsigned)p * 16 * 144);
                MMA_BF16(acc[0][2 * p],     a0, b0, b1);
                MMA_BF16(acc[0][2 * p + 1], a0, b2, b3);
                MMA_BF16(acc[1][2 * p],     a1, b0, b1);
                MMA_BF16(acc[1][2 * p + 1], a1, b2, b3);
            }
        }
        __syncthreads();            // buffer kc&1 free for reuse
        if (kc == 0) load_chunk(2); // prefetch last chunk after first compute
    }

    // Epilogue: d2 = sq_i + sq_j - 2*dot, clamp to +0.
    int g = lane >> 2, t = lane & 3;
    bool offdiag = (bi != bj);
    #pragma unroll
    for (int mt = 0; mt < 2; ++mt) {
        int ia = i0 + m0 + mt * 16 + g;
        float si0 = g_sq[ia], si1 = g_sq[ia + 8];
        #pragma unroll
        for (int nt = 0; nt < 8; ++nt) {
            int jc = j0 + n0 + nt * 8 + t * 2;
            float sj0 = g_sq[jc], sj1 = g_sq[jc + 1];
            float d00 = si0 + sj0 - 2.f * acc[mt][nt][0]; d00 = d00 > 0.f ? d00 : 0.f;
            float d01 = si0 + sj1 - 2.f * acc[mt][nt][1]; d01 = d01 > 0.f ? d01 : 0.f;
            float d10 = si1 + sj0 - 2.f * acc[mt][nt][2]; d10 = d10 > 0.f ? d10 : 0.f;
            float d11 = si1 + sj1 - 2.f * acc[mt][nt][3]; d11 = d11 > 0.f ? d11 : 0.f;
            *(float2*)(g_d2 + (size_t)ia * B + jc)       = make_float2(d00, d01);
            *(float2*)(g_d2 + (size_t)(ia + 8) * B + jc) = make_float2(d10, d11);
            if (offdiag) {
                g_d2[(size_t)jc * B + ia]           = d00;
                g_d2[(size_t)(jc + 1) * B + ia]     = d01;
                g_d2[(size_t)jc * B + ia + 8]       = d10;
                g_d2[(size_t)(jc + 1) * B + ia + 8] = d11;
            }
        }
    }
}

// ---------------------------------------------------------------------------
// Per-row selection + neighborhood entropy (R5 pruned scheme, DRAM-leaning).
// ---------------------------------------------------------------------------
__global__ void __launch_bounds__(TPB_SEL) select_kernel(const int* __restrict__ kptr,
                                                         float* __restrict__ out_ent,
                                                         int B, int C) {
    int i    = blockIdx.x;
    int tid  = threadIdx.x;
    int lane = tid & 31;
    int wid  = tid >> 5;

    int k = *kptr;
    if (k > B / 4) k = B / 4;
    int kk = k + 1;

    __shared__ unsigned sm_min[TPB_SEL];
    __shared__ unsigned cand[CAP];
    __shared__ int      ncand;
    __shared__ unsigned sh_tub, sh_kth;
    __shared__ int      counts[64];
    __shared__ int      sred[8];

    const uint4* row4 = (const uint4*)(g_d2 + (size_t)i * B);
    unsigned v[32];
    unsigned mn = 0xffffffffu;
    #pragma unroll
    for (int s = 0; s < 8; ++s) {
        uint4 q = row4[tid + s * TPB_SEL];
        v[4 * s + 0] = q.x; v[4 * s + 1] = q.y;
        v[4 * s + 2] = q.z; v[4 * s + 3] = q.w;
        unsigned m01 = min(q.x, q.y), m23 = min(q.z, q.w);
        mn = min(mn, min(m01, m23));
    }
    sm_min[tid] = mn;
    if (tid < 64) counts[tid] = 0;
    if (tid == 0) ncand = 0;
    __syncthreads();

    if (wid == 0) {
        unsigned tub;
        if (kk <= 32) {
            unsigned m = sm_min[lane];
            #pragma unroll
            for (int s = 1; s < 8; ++s) m = min(m, sm_min[lane + 32 * s]);
            int cls = 0, cle = 0;
            #pragma unroll
            for (int j = 0; j < 32; ++j) {
                unsigned b = __shfl_sync(0xffffffffu, m, j);
                cls += (b < m);
                cle += (b <= m);
            }
            bool sel = (cls < kk) && (cle >= kk);
            unsigned ball = __ballot_sync(0xffffffffu, sel);
            tub = __shfl_sync(0xffffffffu, m, __ffs(ball) - 1);
        } else {
            tub = 0xffffffffu;
        }
        if (lane == 0) sh_tub = tub;
    }
    __syncthreads();

    unsigned tub = sh_tub;
    bool fullscan = (tub == 0xffffffffu);
    if (!fullscan) {
        #pragma unroll
        for (int s = 0; s < 32; ++s) {
            if (v[s] <= tub) {
                int p = atomicAdd(&ncand, 1);
                if (p < CAP) cand[p] = v[s];
            }
        }
    }
    __syncthreads();

    int n = ncand;
    if (fullscan || n > CAP) {
        unsigned prefix = 0u;
        for (int b = 30; b >= 0; --b) {
            unsigned tcand = prefix | (1u << b);
            int c = 0;
            #pragma unroll
            for (int s = 0; s < 32; ++s) c += (v[s] < tcand);
            #pragma unroll
            for (int off = 16; off; off >>= 1) c += __shfl_xor_sync(0xffffffffu, c, off);
            if (lane == 0) sred[wid] = c;
            __syncthreads();
            int tot = sred[0] + sred[1] + sred[2] + sred[3] +
                      sred[4] + sred[5] + sred[6] + sred[7];
            if (tot < kk) prefix = tcand;
            __syncthreads();
        }
        if (tid == 0) sh_kth = prefix;
    } else if (wid == 0) {
        unsigned kth;
        if (n <= 32) {
            unsigned c = (lane < n) ? cand[lane] : 0xffffffffu;
            int cls = 0, cle = 0;
            for (int j = 0; j < n; ++j) {
                unsigned b = __shfl_sync(0xffffffffu, c, j);
                cls += (b < c);
                cle += (b <= c);
            }
            bool sel = (cls < kk) && (cle >= kk);
            unsigned ball = __ballot_sync(0xffffffffu, sel);
            kth = __shfl_sync(0xffffffffu, c, __ffs(ball) - 1);
        } else {
            unsigned prefix = 0u;
            for (int b = 30; b >= 0; --b) {
                unsigned tcand = prefix | (1u << b);
                int cc = 0;
                for (int idx = lane; idx < n; idx += 32) cc += (cand[idx] < tcand);
                #pragma unroll
                for (int off = 16; off; off >>= 1) cc += __shfl_xor_sync(0xffffffffu, cc, off);
                if (cc < kk) prefix = tcand;
            }
            kth = prefix;
        }
        if (lane == 0) sh_kth = kth;
    }
    __syncthreads();

    unsigned kth = sh_kth;
    #pragma unroll
    for (int s = 0; s < 32; ++s) {
        if (v[s] < kth) {
            int j = 4 * (tid + (s >> 2) * TPB_SEL) + (s & 3);
            atomicAdd(&counts[g_hard[j]], 1);
        }
    }
    __syncthreads();

    if (wid == 0) {
        float cnt = (lane < C) ? (float)counts[lane] : 0.f;
        float nn = cnt;
        #pragma unroll
        for (int off = 16; off; off >>= 1) nn += __shfl_xor_sync(0xffffffffu, nn, off);
        float ni = (nn > 1.f) ? nn : 1.f;
        float bfrac = cnt / ni;
        float h = -bfrac * logf(bfrac + 1e-5f);
        #pragma unroll
        for (int off = 16; off; off >>= 1) h += __shfl_xor_sync(0xffffffffu, h, off);
        if (lane == 0) out_ent[i] = h;
    }
}

// ---------------------------------------------------------------------------
__global__ void finalize_kernel(float* __restrict__ out2, int B, int C) {
    int lane = threadIdx.x;
    float g  = (lane < C) ? (float)g_gcounts[lane] : 0.f;
    float gb = g / (float)B;
    float h  = -gb * logf(gb + 1e-5f);
    float p  = (lane < C && g > 0.f) ? 1.f : 0.f;
    #pragma unroll
    for (int off = 16; off; off >>= 1) {
        h += __shfl_xor_sync(0xffffffffu, h, off);
        p += __shfl_xor_sync(0xffffffffu, p, off);
    }
    if (lane == 0) { out2[0] = h; out2[1] = p; }
}

// ---------------------------------------------------------------------------
// Output layout (flattened reference tuple):
//   [0, B*64)            encodings passthrough
//   [B*64, B*64+B)       neighbourhood_entropy
//   [B*64+B]             cluster_size_entropy
//   [B*64+B+1]           n_populated
//   [B*64+B+2, +B)       max_groups
// ---------------------------------------------------------------------------
extern "C" void kernel_launch(void* const* d_in, const int* in_sizes, int n_in,
                              void* d_out, int out_size) {
    const float* E    = (const float*)d_in[0];
    const float* Cat  = (const float*)d_in[1];
    const int*   kptr = (const int*)d_in[2];

    int B = in_sizes[0] / DIMS;
    int C = in_sizes[1] / B;

    float* out      = (float*)d_out;
    float* out_ent  = out + (size_t)B * DIMS;
    float* out_sc   = out_ent + B;
    float* out_maxg = out_sc + 2;

    cudaMemcpyAsync(out, E, (size_t)B * DIMS * sizeof(float),
                    cudaMemcpyDeviceToDevice, 0);

    cudaFuncSetAttribute(mma_gemm_kernel,
                         cudaFuncAttributeMaxDynamicSharedMemorySize, SMEM_BYTES);

    int nb = B / 128;
    int ntri = nb * (nb + 1) / 2;

    zero_kernel<<<1, 64>>>();
    convert_kernel<<<(B * DIMS + 255) / 256, 256>>>(E, B);
    stats_kernel<<<(B * 32 + 255) / 256, 256>>>(E, Cat, out_maxg, B, C);
    mma_gemm_kernel<<<ntri, 256, SMEM_BYTES>>>(B);
    select_kernel<<<B, TPB_SEL>>>(kptr, out_ent, B, C);
    finalize_kernel<<<1, 32>>>(out_sc, B, C);
}

// round 10
// speedup vs baseline: 4.2761x; 1.1499x over previous
#include <cuda_runtime.h>
#include <cuda_bf16.h>
#include <math.h>

#define DIMS 64
#define MAXB 8192
#define TPB_SEL 256
#define CAP2 1024         // candidate buffer (expected ~20-40 entries)
#define KCAT 192          // [hi(64) | lo(64) | hi(64)] x [hi | hi | lo]
#define CH_BYTES 18432    // 128 rows x 144B per tile-chunk
#define SMEM_BYTES (2 * 2 * CH_BYTES)   // 2 buffers x (A + B) = 73728 B

// Scratch (static device allocations are the sanctioned scratch mechanism).
static __device__ float g_d2[(size_t)MAXB * (size_t)MAXB];    // 256 MB
static __device__ unsigned g_tmin[(size_t)MAXB * 64];         // 2 MB per-(row,tile) min
static __device__ float g_sq[MAXB];
static __device__ int   g_hard[MAXB];
static __device__ int   g_gcounts[64];
static __device__ __nv_bfloat16 g_Acat[(size_t)MAXB * KCAT];  // 3.1 MB
static __device__ __nv_bfloat16 g_Bcat[(size_t)MAXB * KCAT];  // 3.1 MB

// ---------------------------------------------------------------------------
__global__ void zero_kernel() {
    if (threadIdx.x < 64) g_gcounts[threadIdx.x] = 0;
}

// ---------------------------------------------------------------------------
// Split fp32 -> bf16 hi+lo, build concatenated operands:
//   dot(Acat_i, Bcat_j) = hi.hi + lo.hi + hi.lo  (= x.y - lo.lo, |lo.lo|~1e-7)
// ---------------------------------------------------------------------------
__global__ void convert_kernel(const float* __restrict__ E, int B) {
    int idx = blockIdx.x * blockDim.x + threadIdx.x;
    if (idx >= B * DIMS) return;
    int i = idx >> 6, d = idx & 63;
    float x = E[idx];
    __nv_bfloat16 hi = __float2bfloat16(x);
    __nv_bfloat16 lo = __float2bfloat16(x - __bfloat162float(hi));
    size_t base = (size_t)i * KCAT;
    g_Acat[base + d]       = hi;
    g_Acat[base + 64 + d]  = lo;
    g_Acat[base + 128 + d] = hi;
    g_Bcat[base + d]       = hi;
    g_Bcat[base + 64 + d]  = hi;
    g_Bcat[base + 128 + d] = lo;
}

// ---------------------------------------------------------------------------
// Per-row: squared norm, argmax/max of categorical, global cluster counts.
// ---------------------------------------------------------------------------
__global__ void stats_kernel(const float* __restrict__ E,
                             const float* __restrict__ Cat,
                             float* __restrict__ out_maxg,
                             int B, int C) {
    int warp = (blockIdx.x * blockDim.x + threadIdx.x) >> 5;
    int lane = threadIdx.x & 31;
    if (warp >= B) return;

    float v0 = E[(size_t)warp * DIMS + lane];
    float v1 = E[(size_t)warp * DIMS + 32 + lane];
    float s = v0 * v0 + v1 * v1;
    #pragma unroll
    for (int off = 16; off; off >>= 1) s += __shfl_xor_sync(0xffffffffu, s, off);

    float mv = -INFINITY;
    int   mi = 0x7fffffff;
    for (int c = lane; c < C; c += 32) {
        float x = Cat[(size_t)warp * C + c];
        if (x > mv) { mv = x; mi = c; }
    }
    #pragma unroll
    for (int off = 16; off; off >>= 1) {
        float ov = __shfl_xor_sync(0xffffffffu, mv, off);
        int   oi = __shfl_xor_sync(0xffffffffu, mi, off);
        if (ov > mv || (ov == mv && oi < mi)) { mv = ov; mi = oi; }
    }

    if (lane == 0) {
        g_sq[warp]   = s;
        g_hard[warp] = mi;
        out_maxg[warp] = mv;
        atomicAdd(&g_gcounts[mi], 1);
    }
}

// ---------------------------------------------------------------------------
__device__ __forceinline__ void ldsm_x4(unsigned& r0, unsigned& r1,
                                        unsigned& r2, unsigned& r3, unsigned a) {
    asm volatile("ldmatrix.sync.aligned.m8n8.x4.shared.b16 {%0,%1,%2,%3}, [%4];"
                 : "=r"(r0), "=r"(r1), "=r"(r2), "=r"(r3) : "r"(a));
}
__device__ __forceinline__ void cp16(unsigned saddr, const void* gaddr) {
    asm volatile("cp.async.cg.shared.global [%0], [%1], 16;"
                 :: "r"(saddr), "l"(gaddr));
}
#define MMA_BF16(ACC, A, B0, B1)                                             \
    asm volatile(                                                            \
        "mma.sync.aligned.m16n8k16.row.col.f32.bf16.bf16.f32 "               \
        "{%0,%1,%2,%3}, {%4,%5,%6,%7}, {%8,%9}, {%0,%1,%2,%3};\n"            \
        : "+f"((ACC)[0]), "+f"((ACC)[1]), "+f"((ACC)[2]), "+f"((ACC)[3])     \
        : "r"((A)[0]), "r"((A)[1]), "r"((A)[2]), "r"((A)[3]),                \
          "r"(B0), "r"(B1))

// ---------------------------------------------------------------------------
// Symmetric tensor-core GEMM (triangle-only grid), double-buffered cp.async
// pipeline. Epilogue additionally emits per-(row, column-tile) minima into
// g_tmin (straight tile -> row minima; transposed -> column minima).
// ---------------------------------------------------------------------------
__global__ void __launch_bounds__(256, 2) mma_gemm_kernel(int B) {
    extern __shared__ __align__(16) char smem[];
    __shared__ unsigned smin_row[128];
    __shared__ unsigned smin_col[128];

    // triangular decode: block x -> (bi >= bj)
    int x = blockIdx.x;
    int bi = (int)((sqrtf(8.0f * (float)x + 1.0f) - 1.0f) * 0.5f);
    while ((bi + 1) * (bi + 2) / 2 <= x) ++bi;
    while (bi * (bi + 1) / 2 > x) --bi;
    int bj = x - bi * (bi + 1) / 2;
    int i0 = bi * 128, j0 = bj * 128;

    int tid = threadIdx.x;
    int wid = tid >> 5, lane = tid & 31;
    int m0 = (wid >> 1) * 32;     // warp_m: 0..3
    int n0 = (wid & 1) * 64;      // warp_n: 0..1

    if (tid < 128) smin_row[tid] = 0xffffffffu;
    else           smin_col[tid - 128] = 0xffffffffu;

    unsigned sbase;
    asm("{ .reg .u64 t; cvta.to.shared.u64 t, %1; cvt.u32.u64 %0, t; }"
        : "=r"(sbase) : "l"(smem));
    const char* gA = (const char*)g_Acat;
    const char* gB = (const char*)g_Bcat;

    unsigned aoff = (unsigned)(m0 + (lane & 15)) * 144 + ((lane >> 4) * 16);
    unsigned boff = (unsigned)(n0 + (lane & 7) + ((lane >> 4) << 3)) * 144
                  + (((lane >> 3) & 1) * 16);

    float acc[2][8][4];
    #pragma unroll
    for (int mt = 0; mt < 2; ++mt)
        #pragma unroll
        for (int nt = 0; nt < 8; ++nt)
            #pragma unroll
            for (int r = 0; r < 4; ++r) acc[mt][nt][r] = 0.f;

    auto load_chunk = [&](int kc) {
        unsigned sA = sbase + (unsigned)(kc & 1) * (2 * CH_BYTES);
        unsigned sB = sA + CH_BYTES;
        #pragma unroll
        for (int it = 0; it < 4; ++it) {
            int idx = it * 256 + tid;
            int r = idx >> 3, c = idx & 7;
            cp16(sA + r * 144 + c * 16, gA + (size_t)(i0 + r) * 384 + kc * 128 + c * 16);
            cp16(sB + r * 144 + c * 16, gB + (size_t)(j0 + r) * 384 + kc * 128 + c * 16);
        }
        asm volatile("cp.async.commit_group;");
    };

    load_chunk(0);
    load_chunk(1);

    #pragma unroll
    for (int kc = 0; kc < 3; ++kc) {
        if (kc < 2) asm volatile("cp.async.wait_group 1;");
        else        asm volatile("cp.async.wait_group 0;");
        __syncthreads();

        unsigned sA = sbase + (unsigned)(kc & 1) * (2 * CH_BYTES);
        unsigned sB = sA + CH_BYTES;
        unsigned aab = sA + aoff, bab = sB + boff;

        #pragma unroll
        for (int ks = 0; ks < 4; ++ks) {
            unsigned kb = ks * 32;
            unsigned a0[4], a1[4];
            ldsm_x4(a0[0], a0[1], a0[2], a0[3], aab + kb);
            ldsm_x4(a1[0], a1[1], a1[2], a1[3], aab + kb + 16 * 144);
            #pragma unroll
            for (int p = 0; p < 4; ++p) {
                unsigned b0, b1, b2, b3;
                ldsm_x4(b0, b1, b2, b3, bab + kb + (unsigned)p * 16 * 144);
                MMA_BF16(acc[0][2 * p],     a0, b0, b1);
                MMA_BF16(acc[0][2 * p + 1], a0, b2, b3);
                MMA_BF16(acc[1][2 * p],     a1, b0, b1);
                MMA_BF16(acc[1][2 * p + 1], a1, b2, b3);
            }
        }
        __syncthreads();
        if (kc == 0) load_chunk(2);
    }

    // Epilogue: d2 = sq_i + sq_j - 2*dot (clamped to +0) + tile minima.
    int g = lane >> 2, t = lane & 3;
    bool offdiag = (bi != bj);
    float cmin[8][2];
    #pragma unroll
    for (int nt = 0; nt < 8; ++nt) { cmin[nt][0] = INFINITY; cmin[nt][1] = INFINITY; }

    #pragma unroll
    for (int mt = 0; mt < 2; ++mt) {
        int ia = i0 + m0 + mt * 16 + g;
        float si0 = g_sq[ia], si1 = g_sq[ia + 8];
        float rmin0 = INFINITY, rmin1 = INFINITY;
        #pragma unroll
        for (int nt = 0; nt < 8; ++nt) {
            int jc = j0 + n0 + nt * 8 + t * 2;
            float sj0 = g_sq[jc], sj1 = g_sq[jc + 1];
            float d00 = si0 + sj0 - 2.f * acc[mt][nt][0]; d00 = d00 > 0.f ? d00 : 0.f;
            float d01 = si0 + sj1 - 2.f * acc[mt][nt][1]; d01 = d01 > 0.f ? d01 : 0.f;
            float d10 = si1 + sj0 - 2.f * acc[mt][nt][2]; d10 = d10 > 0.f ? d10 : 0.f;
            float d11 = si1 + sj1 - 2.f * acc[mt][nt][3]; d11 = d11 > 0.f ? d11 : 0.f;
            *(float2*)(g_d2 + (size_t)ia * B + jc)       = make_float2(d00, d01);
            *(float2*)(g_d2 + (size_t)(ia + 8) * B + jc) = make_float2(d10, d11);
            if (offdiag) {
                g_d2[(size_t)jc * B + ia]           = d00;
                g_d2[(size_t)(jc + 1) * B + ia]     = d01;
                g_d2[(size_t)jc * B + ia + 8]       = d10;
                g_d2[(size_t)(jc + 1) * B + ia + 8] = d11;
            }
            rmin0 = fminf(rmin0, fminf(d00, d01));
            rmin1 = fminf(rmin1, fminf(d10, d11));
            cmin[nt][0] = fminf(cmin[nt][0], fminf(d00, d10));
            cmin[nt][1] = fminf(cmin[nt][1], fminf(d01, d11));
        }
        // reduce row minima across the 4 t-lanes sharing a row
        rmin0 = fminf(rmin0, __shfl_xor_sync(0xffffffffu, rmin0, 1));
        rmin0 = fminf(rmin0, __shfl_xor_sync(0xffffffffu, rmin0, 2));
        rmin1 = fminf(rmin1, __shfl_xor_sync(0xffffffffu, rmin1, 1));
        rmin1 = fminf(rmin1, __shfl_xor_sync(0xffffffffu, rmin1, 2));
        if (t == 0) {
            atomicMin(&smin_row[m0 + mt * 16 + g],     __float_as_uint(rmin0));
            atomicMin(&smin_row[m0 + mt * 16 + g + 8], __float_as_uint(rmin1));
        }
    }
    if (offdiag) {
        #pragma unroll
        for (int nt = 0; nt < 8; ++nt) {
            #pragma unroll
            for (int h = 0; h < 2; ++h) {
                float cm = cmin[nt][h];
                cm = fminf(cm, __shfl_xor_sync(0xffffffffu, cm, 4));
                cm = fminf(cm, __shfl_xor_sync(0xffffffffu, cm, 8));
                cm = fminf(cm, __shfl_xor_sync(0xffffffffu, cm, 16));
                if (g == 0)
                    atomicMin(&smin_col[n0 + nt * 8 + t * 2 + h], __float_as_uint(cm));
            }
        }
    }
    __syncthreads();
    if (tid < 128)       g_tmin[(size_t)(i0 + tid) * 64 + bj] = smin_row[tid];
    else if (offdiag)    g_tmin[(size_t)(j0 + tid - 128) * 64 + bi] = smin_col[tid - 128];
}

// ---------------------------------------------------------------------------
// Per-row selection + entropy using tile-minima pruning:
//  T_ub = kk-th smallest of the 64 tile minima (guaranteed >= global kk-th).
//  Only tiles with min <= T_ub can hold candidates / histogram members.
// ---------------------------------------------------------------------------
__global__ void __launch_bounds__(TPB_SEL) select_kernel(const int* __restrict__ kptr,
                                                         float* __restrict__ out_ent,
                                                         int B, int C) {
    int i    = blockIdx.x;
    int tid  = threadIdx.x;
    int lane = tid & 31;
    int wid  = tid >> 5;

    int k = *kptr;
    if (k > B / 4) k = B / 4;
    int kk = k + 1;
    int ntile = B >> 7;                 // 64 for B=8192 (<= 64 by MAXB)

    __shared__ unsigned s_tmin[64];
    __shared__ unsigned candv[CAP2];
    __shared__ int      candj[CAP2];
    __shared__ int      ncand;
    __shared__ unsigned sh_tub, sh_kth;
    __shared__ int      counts[64];
    __shared__ int      sred[8];

    if (tid < 64) {
        s_tmin[tid] = (tid < ntile) ? g_tmin[(size_t)i * 64 + tid] : 0xffffffffu;
        counts[tid] = 0;
    }
    if (tid == 0) ncand = 0;
    __syncthreads();

    const float* row = g_d2 + (size_t)i * B;

    // ---- Phase 1: T_ub = exact kk-th smallest of the tile minima ----
    if (wid == 0) {
        unsigned tub = 0xffffffffu;     // sentinel -> fallback
        if (kk <= ntile) {
            unsigned m0v = s_tmin[lane], m1v = s_tmin[lane + 32];
            int cls0 = 0, cle0 = 0, cls1 = 0, cle1 = 0;
            #pragma unroll
            for (int j = 0; j < 64; ++j) {
                unsigned b = __shfl_sync(0xffffffffu, (j < 32) ? m0v : m1v, j & 31);
                cls0 += (b < m0v);  cle0 += (b <= m0v);
                cls1 += (b < m1v);  cle1 += (b <= m1v);
            }
            bool sel0 = (cls0 < kk) && (cle0 >= kk);
            bool sel1 = (cls1 < kk) && (cle1 >= kk);
            unsigned bal0 = __ballot_sync(0xffffffffu, sel0);
            unsigned bal1 = __ballot_sync(0xffffffffu, sel1);
            if (bal0)      tub = __shfl_sync(0xffffffffu, m0v, __ffs(bal0) - 1);
            else if (bal1) tub = __shfl_sync(0xffffffffu, m1v, __ffs(bal1) - 1);
        }
        if (lane == 0) sh_tub = tub;
    }
    __syncthreads();

    unsigned tub = sh_tub;
    bool fallback = (tub == 0xffffffffu);

    if (!fallback) {
        // ---- Phase 2: gather candidates from tiles with min <= T_ub ----
        for (int c = wid; c < ntile; c += 8) {
            if (s_tmin[c] <= tub) {
                uint4 q = ((const uint4*)row)[c * 32 + lane];
                int jb = c * 128 + lane * 4;
                if (q.x <= tub) { int p = atomicAdd(&ncand, 1); if (p < CAP2) { candv[p] = q.x; candj[p] = jb;     } }
                if (q.y <= tub) { int p = atomicAdd(&ncand, 1); if (p < CAP2) { candv[p] = q.y; candj[p] = jb + 1; } }
                if (q.z <= tub) { int p = atomicAdd(&ncand, 1); if (p < CAP2) { candv[p] = q.z; candj[p] = jb + 2; } }
                if (q.w <= tub) { int p = atomicAdd(&ncand, 1); if (p < CAP2) { candv[p] = q.w; candj[p] = jb + 3; } }
            }
        }
        __syncthreads();
        if (ncand > CAP2) fallback = true;      // block-uniform (shared value)
    }

    if (!fallback) {
        int n = ncand;
        // ---- Phase 3: exact global kk-th among candidates ----
        if (wid == 0) {
            unsigned kth;
            if (n <= 32) {
                unsigned c = (lane < n) ? candv[lane] : 0xffffffffu;
                int cls = 0, cle = 0;
                for (int j = 0; j < n; ++j) {
                    unsigned b = __shfl_sync(0xffffffffu, c, j);
                    cls += (b < c);
                    cle += (b <= c);
                }
                bool sel = (cls < kk) && (cle >= kk);
                unsigned ball = __ballot_sync(0xffffffffu, sel);
                kth = __shfl_sync(0xffffffffu, c, __ffs(ball) - 1);
            } else {
                unsigned prefix = 0u;
                for (int b = 30; b >= 0; --b) {
                    unsigned tc = prefix | (1u << b);
                    int cc = 0;
                    for (int idx = lane; idx < n; idx += 32) cc += (candv[idx] < tc);
                    #pragma unroll
                    for (int off = 16; off; off >>= 1) cc += __shfl_xor_sync(0xffffffffu, cc, off);
                    if (cc < kk) prefix = tc;
                }
                kth = prefix;
            }
            if (lane == 0) sh_kth = kth;
        }
        __syncthreads();

        // ---- Phase 4: histogram over candidates (strict <) ----
        unsigned kth = sh_kth;
        for (int p = tid; p < n; p += TPB_SEL)
            if (candv[p] < kth) atomicAdd(&counts[g_hard[candj[p]]], 1);
        __syncthreads();
    } else {
        // ---- Generic slow-but-correct path (kk > ntile or overflow) ----
        __syncthreads();
        unsigned prefix = 0u;
        for (int b = 30; b >= 0; --b) {
            unsigned tc = prefix | (1u << b);
            int c = 0;
            for (int j = tid; j < B; j += TPB_SEL)
                c += (__float_as_uint(row[j]) < tc);
            #pragma unroll
            for (int off = 16; off; off >>= 1) c += __shfl_xor_sync(0xffffffffu, c, off);
            if (lane == 0) sred[wid] = c;
            __syncthreads();
            int tot = sred[0] + sred[1] + sred[2] + sred[3] +
                      sred[4] + sred[5] + sred[6] + sred[7];
            if (tot < kk) prefix = tc;
            __syncthreads();
        }
        for (int j = tid; j < B; j += TPB_SEL)
            if (__float_as_uint(row[j]) < prefix)
                atomicAdd(&counts[g_hard[j]], 1);
        __syncthreads();
    }

    // ---- entropy ----
    if (wid == 0) {
        float cnt = (lane < C) ? (float)counts[lane] : 0.f;
        float nn = cnt;
        #pragma unroll
        for (int off = 16; off; off >>= 1) nn += __shfl_xor_sync(0xffffffffu, nn, off);
        float ni = (nn > 1.f) ? nn : 1.f;
        float bfrac = cnt / ni;
        float h = -bfrac * logf(bfrac + 1e-5f);
        #pragma unroll
        for (int off = 16; off; off >>= 1) h += __shfl_xor_sync(0xffffffffu, h, off);
        if (lane == 0) out_ent[i] = h;
    }
}

// ---------------------------------------------------------------------------
__global__ void finalize_kernel(float* __restrict__ out2, int B, int C) {
    int lane = threadIdx.x;
    float g  = (lane < C) ? (float)g_gcounts[lane] : 0.f;
    float gb = g / (float)B;
    float h  = -gb * logf(gb + 1e-5f);
    float p  = (lane < C && g > 0.f) ? 1.f : 0.f;
    #pragma unroll
    for (int off = 16; off; off >>= 1) {
        h += __shfl_xor_sync(0xffffffffu, h, off);
        p += __shfl_xor_sync(0xffffffffu, p, off);
    }
    if (lane == 0) { out2[0] = h; out2[1] = p; }
}

// ---------------------------------------------------------------------------
// Output layout (flattened reference tuple):
//   [0, B*64)            encodings passthrough
//   [B*64, B*64+B)       neighbourhood_entropy
//   [B*64+B]             cluster_size_entropy
//   [B*64+B+1]           n_populated
//   [B*64+B+2, +B)       max_groups
// ---------------------------------------------------------------------------
extern "C" void kernel_launch(void* const* d_in, const int* in_sizes, int n_in,
                              void* d_out, int out_size) {
    const float* E    = (const float*)d_in[0];
    const float* Cat  = (const float*)d_in[1];
    const int*   kptr = (const int*)d_in[2];

    int B = in_sizes[0] / DIMS;
    int C = in_sizes[1] / B;

    float* out      = (float*)d_out;
    float* out_ent  = out + (size_t)B * DIMS;
    float* out_sc   = out_ent + B;
    float* out_maxg = out_sc + 2;

    cudaMemcpyAsync(out, E, (size_t)B * DIMS * sizeof(float),
                    cudaMemcpyDeviceToDevice, 0);

    cudaFuncSetAttribute(mma_gemm_kernel,
                         cudaFuncAttributeMaxDynamicSharedMemorySize, SMEM_BYTES);

    int nb = B / 128;
    int ntri = nb * (nb + 1) / 2;

    zero_kernel<<<1, 64>>>();
    convert_kernel<<<(B * DIMS + 255) / 256, 256>>>(E, B);
    stats_kernel<<<(B * 32 + 255) / 256, 256>>>(E, Cat, out_maxg, B, C);
    mma_gemm_kernel<<<ntri, 256, SMEM_BYTES>>>(B);
    select_kernel<<<B, TPB_SEL>>>(kptr, out_ent, B, C);
    finalize_kernel<<<1, 32>>>(out_sc, B, C);
}